// round 4
// baseline (speedup 1.0000x reference)
#include <cuda_runtime.h>
#include <math.h>

// Problem constants
#define kB   2
#define kS   1024
#define kD   1024
#define kH   16
#define kHD  64
#define kFF  4096
#define kV   32000
#define kR   16
#define kL   2
#define kM   2048          /* B*S */
#define kBH  32            /* B*H */
#define LORA_S 2.0f
#define RMS_EPS 1e-6f

// ---------------------------------------------------------------------------
// Device scratch
// ---------------------------------------------------------------------------
__device__ float g_x [kM*kD];
__device__ float g_dx[kM*kD];
__device__ float g_h [kM*kD];
__device__ float g_dh[kM*kD];
__device__ float g_q [kM*kD];
__device__ float g_k [kM*kD];
__device__ float g_v [kM*kD];
__device__ float g_dq[kM*kD];
__device__ float g_dk[kM*kD];
__device__ float g_dv[kM*kD];
__device__ float g_o [kM*kD];
__device__ float g_do[kM*kD];
__device__ float g_u [kM*kFF];
__device__ float g_du[kM*kFF];
__device__ float g_sc [kBH*kS*kS];
__device__ float g_dsc[kBH*kS*kS];
__device__ float g_t [kM*kR];

// ---------------------------------------------------------------------------
// Embedding lookup + zero tangent
// ---------------------------------------------------------------------------
__global__ void embed_kernel(const int* __restrict__ ids,
                             const float* __restrict__ emb,
                             float* __restrict__ x, float* __restrict__ dx)
{
    int m = blockIdx.y;
    int d = blockIdx.x * 256 + threadIdx.x;
    int id = ids[m];
    x [(size_t)m*kD + d] = emb[(size_t)id*kD + d];
    dx[(size_t)m*kD + d] = 0.0f;
}

// ---------------------------------------------------------------------------
// RMSNorm JVP
// ---------------------------------------------------------------------------
__global__ void rms_jvp_kernel(const float* __restrict__ x,
                               const float* __restrict__ dx,
                               const float* __restrict__ g,
                               float* __restrict__ h, float* __restrict__ dh,
                               int sum_mode)
{
    int m = blockIdx.x;
    const float* xr  = x  + (size_t)m*kD;
    const float* dxr = dx + (size_t)m*kD;
    int t = threadIdx.x;   // 256
    float xv[4], dv[4];
    float s2 = 0.f, sxd = 0.f;
#pragma unroll
    for (int i = 0; i < 4; i++) {
        int d = t + i*256;
        xv[i] = xr[d]; dv[i] = dxr[d];
        s2  += xv[i]*xv[i];
        sxd += xv[i]*dv[i];
    }
    __shared__ float shA[8], shB[8], bc[2];
#pragma unroll
    for (int o = 16; o > 0; o >>= 1) {
        s2  += __shfl_xor_sync(0xffffffffu, s2 , o);
        sxd += __shfl_xor_sync(0xffffffffu, sxd, o);
    }
    int w = t >> 5;
    if ((t & 31) == 0) { shA[w] = s2; shB[w] = sxd; }
    __syncthreads();
    if (t < 32) {
        float a = (t < 8) ? shA[t] : 0.f;
        float b = (t < 8) ? shB[t] : 0.f;
#pragma unroll
        for (int o = 4; o > 0; o >>= 1) {
            a += __shfl_xor_sync(0xffffffffu, a, o);
            b += __shfl_xor_sync(0xffffffffu, b, o);
        }
        if (t == 0) { bc[0] = a; bc[1] = b; }
    }
    __syncthreads();
    float m2 = bc[0] * (1.0f/kD) + RMS_EPS;
    float n  = 1.0f / sqrtf(m2);
    float c  = (bc[1] * (1.0f/kD)) / m2;
#pragma unroll
    for (int i = 0; i < 4; i++) {
        int d = t + i*256;
        float gv = g[d];
        if (sum_mode) {
            h[(size_t)m*kD + d] = gv*n*(xv[i] + dv[i] - xv[i]*c);
        } else {
            h [(size_t)m*kD + d] = gv*n*xv[i];
            dh[(size_t)m*kD + d] = gv*n*(dv[i] - xv[i]*c);
        }
    }
}

// ---------------------------------------------------------------------------
// 3xTF32 tensor-core GEMM: C[M,N] (+)= A[M,K] @ B[K,N], row-major.
// BM=128, BN=64, BK=32. 256 threads = 8 warps in 4x2, warp tile 32x32.
// Each input split a = a_hi + a_lo (tf32); C = aH*bH + aH*bL + aL*bH.
// XOR-swizzled SMEM (48KB static), conflict-free fragment loads.
// ---------------------------------------------------------------------------
__device__ __forceinline__ unsigned f2tf32(float x) {
    unsigned r;
    asm("cvt.rna.tf32.f32 %0, %1;" : "=r"(r) : "f"(x));
    return r;
}

__device__ __forceinline__ void mma8(float* c, const unsigned* a, const unsigned* b) {
    asm volatile(
        "mma.sync.aligned.m16n8k8.row.col.f32.tf32.tf32.f32 "
        "{%0,%1,%2,%3}, {%4,%5,%6,%7}, {%8,%9}, {%0,%1,%2,%3};"
        : "+f"(c[0]), "+f"(c[1]), "+f"(c[2]), "+f"(c[3])
        : "r"(a[0]), "r"(a[1]), "r"(a[2]), "r"(a[3]), "r"(b[0]), "r"(b[1]));
}

__global__ void __launch_bounds__(256, 2)
tf32gemm_kernel(const float* __restrict__ A, const float* __restrict__ B,
                float* __restrict__ C, int M, int N, int K, int accum)
{
    __shared__ unsigned AsH[128][32];
    __shared__ unsigned AsL[128][32];
    __shared__ unsigned BsH[64][32];
    __shared__ unsigned BsL[64][32];

    int tid  = threadIdx.x;
    int lane = tid & 31;
    int warp = tid >> 5;
    int wm = warp & 3;        // 0..3 : m
    int wn = warp >> 2;       // 0..1 : n
    int g  = lane >> 2;       // group 0..7
    int t  = lane & 3;        // thread in group

    int row0 = blockIdx.y * 128;
    int col0 = blockIdx.x * 64;
    const float* Ab = A + (size_t)row0 * K;

    float c[2][4][4];
#pragma unroll
    for (int mt = 0; mt < 2; mt++)
#pragma unroll
        for (int nt = 0; nt < 4; nt++)
#pragma unroll
            for (int i = 0; i < 4; i++) c[mt][nt][i] = 0.f;

    for (int k0 = 0; k0 < K; k0 += 32) {
        // ---- fill A tile (128x32): 1024 float4, 4 per thread ----
#pragma unroll
        for (int i = 0; i < 4; i++) {
            int f  = tid + i*256;
            int r  = f >> 3;
            int c4 = (f & 7) * 4;
            float4 v4 = *reinterpret_cast<const float4*>(Ab + (size_t)r*K + k0 + c4);
            float xs[4] = {v4.x, v4.y, v4.z, v4.w};
#pragma unroll
            for (int j = 0; j < 4; j++) {
                unsigned hi = f2tf32(xs[j]);
                unsigned lo = f2tf32(xs[j] - __uint_as_float(hi));
                int col = (c4 + j) ^ (r & 7);
                AsH[r][col] = hi;
                AsL[r][col] = lo;
            }
        }
        // ---- fill B tile (32x64 -> Bs[n][k]): 512 float4, 2 per thread ----
#pragma unroll
        for (int i = 0; i < 2; i++) {
            int f  = tid + i*256;
            int kr = f >> 4;
            int c4 = (f & 15) * 4;
            float4 v4 = *reinterpret_cast<const float4*>(B + (size_t)(k0+kr)*N + col0 + c4);
            float xs[4] = {v4.x, v4.y, v4.z, v4.w};
#pragma unroll
            for (int j = 0; j < 4; j++) {
                int n = c4 + j;
                unsigned hi = f2tf32(xs[j]);
                unsigned lo = f2tf32(xs[j] - __uint_as_float(hi));
                int col = kr ^ (n & 7);
                BsH[n][col] = hi;
                BsL[n][col] = lo;
            }
        }
        __syncthreads();

#pragma unroll
        for (int ks = 0; ks < 4; ks++) {
            int kk  = ks * 8;
            int cA0 = kk + (t ^ g);
            int cA1 = kk + ((t + 4) ^ g);

            unsigned aH[2][4], aL[2][4], bH[4][2], bL[4][2];
#pragma unroll
            for (int mt = 0; mt < 2; mt++) {
                int r0 = wm*32 + mt*16 + g;
                aH[mt][0] = AsH[r0  ][cA0];
                aH[mt][1] = AsH[r0+8][cA0];
                aH[mt][2] = AsH[r0  ][cA1];
                aH[mt][3] = AsH[r0+8][cA1];
                aL[mt][0] = AsL[r0  ][cA0];
                aL[mt][1] = AsL[r0+8][cA0];
                aL[mt][2] = AsL[r0  ][cA1];
                aL[mt][3] = AsL[r0+8][cA1];
            }
#pragma unroll
            for (int nt = 0; nt < 4; nt++) {
                int n0 = wn*32 + nt*8 + g;
                bH[nt][0] = BsH[n0][cA0];
                bH[nt][1] = BsH[n0][cA1];
                bL[nt][0] = BsL[n0][cA0];
                bL[nt][1] = BsL[n0][cA1];
            }
#pragma unroll
            for (int mt = 0; mt < 2; mt++)
#pragma unroll
                for (int nt = 0; nt < 4; nt++) {
                    mma8(c[mt][nt], aH[mt], bH[nt]);
                    mma8(c[mt][nt], aH[mt], bL[nt]);
                    mma8(c[mt][nt], aL[mt], bH[nt]);
                }
        }
        __syncthreads();
    }

    // ---- epilogue ----
#pragma unroll
    for (int mt = 0; mt < 2; mt++) {
#pragma unroll
        for (int nt = 0; nt < 4; nt++) {
            int r0 = row0 + wm*32 + mt*16 + g;
            int cc = col0 + wn*32 + nt*8 + 2*t;
            float* p0 = C + (size_t)r0*N + cc;
            float* p1 = C + (size_t)(r0+8)*N + cc;
            float2 v0 = make_float2(c[mt][nt][0], c[mt][nt][1]);
            float2 v1 = make_float2(c[mt][nt][2], c[mt][nt][3]);
            if (accum) {
                float2 o0 = *reinterpret_cast<float2*>(p0);
                float2 o1 = *reinterpret_cast<float2*>(p1);
                v0.x += o0.x; v0.y += o0.y;
                v1.x += o1.x; v1.y += o1.y;
            }
            *reinterpret_cast<float2*>(p0) = v0;
            *reinterpret_cast<float2*>(p1) = v1;
        }
    }
}

// ---------------------------------------------------------------------------
// LoRA: T[m,r] = sum_d h[m,d] * A0[r,d]
// ---------------------------------------------------------------------------
__global__ void lora_t_kernel(const float* __restrict__ h,
                              const float* __restrict__ A0,
                              float* __restrict__ T)
{
    int m = blockIdx.x, r = blockIdx.y;
    const float* hr = h  + (size_t)m*kD;
    const float* ar = A0 + (size_t)r*kD;
    float s = 0.f;
    for (int d = threadIdx.x; d < kD; d += 128) s += hr[d]*ar[d];
#pragma unroll
    for (int o = 16; o > 0; o >>= 1) s += __shfl_xor_sync(0xffffffffu, s, o);
    __shared__ float sh[4];
    if ((threadIdx.x & 31) == 0) sh[threadIdx.x >> 5] = s;
    __syncthreads();
    if (threadIdx.x == 0) T[(size_t)m*kR + r] = sh[0]+sh[1]+sh[2]+sh[3];
}

__global__ void lora_add_kernel(const float* __restrict__ T,
                                const float* __restrict__ Bm,
                                float* __restrict__ dq)
{
    int m = blockIdx.y;
    int n = blockIdx.x * 256 + threadIdx.x;
    __shared__ float ts[kR];
    if (threadIdx.x < kR) ts[threadIdx.x] = T[(size_t)m*kR + threadIdx.x];
    __syncthreads();
    float s = 0.f;
#pragma unroll
    for (int r = 0; r < kR; r++) s += ts[r]*Bm[(size_t)n*kR + r];
    dq[(size_t)m*kD + n] += LORA_S * s;
}

// ---------------------------------------------------------------------------
// Attention scores JVP
// ---------------------------------------------------------------------------
__global__ void __launch_bounds__(256)
attn_scores_kernel(const float* __restrict__ q, const float* __restrict__ k,
                   const float* __restrict__ dq, const float* __restrict__ dk,
                   float* __restrict__ sc, float* __restrict__ dsc)
{
    int jt = blockIdx.x, it = blockIdx.y, bh = blockIdx.z;
    if (jt > it) return;
    int b = bh >> 4, hh = bh & 15;
    size_t base = (size_t)b*kS*kD + (size_t)hh*kHD;
    const float* qb  = q  + base;
    const float* kb  = k  + base;
    const float* dqb = dq + base;
    const float* dkb = dk + base;
    float* sb  = sc  + (size_t)bh*kS*kS;
    float* dsb = dsc + (size_t)bh*kS*kS;
    int i0 = it*64, j0 = jt*64;

    __shared__ float Qs[16][64], dQs[16][64], Ks[16][64], dKs[16][64];
    int tid = threadIdx.x, tx = tid & 15, ty = tid >> 4;
    float acc[4][4], dacc[4][4];
#pragma unroll
    for (int i = 0; i < 4; i++)
#pragma unroll
        for (int j = 0; j < 4; j++) { acc[i][j] = 0.f; dacc[i][j] = 0.f; }

    for (int kc = 0; kc < kHD; kc += 16) {
#pragma unroll
        for (int i = 0; i < 4; i++) {
            int idx = tid + i*256;
            int rr = idx >> 4, cc = idx & 15;
            Qs [cc][rr] = qb [(size_t)(i0+rr)*kD + kc + cc];
            dQs[cc][rr] = dqb[(size_t)(i0+rr)*kD + kc + cc];
            Ks [cc][rr] = kb [(size_t)(j0+rr)*kD + kc + cc];
            dKs[cc][rr] = dkb[(size_t)(j0+rr)*kD + kc + cc];
        }
        __syncthreads();
#pragma unroll
        for (int d = 0; d < 16; d++) {
            float a[4], da[4], bv[4], dbv[4];
#pragma unroll
            for (int i = 0; i < 4; i++) { a[i] = Qs[d][ty*4+i]; da[i] = dQs[d][ty*4+i]; }
#pragma unroll
            for (int j = 0; j < 4; j++) { bv[j] = Ks[d][tx*4+j]; dbv[j] = dKs[d][tx*4+j]; }
#pragma unroll
            for (int i = 0; i < 4; i++)
#pragma unroll
                for (int j = 0; j < 4; j++) {
                    acc [i][j] += a[i]*bv[j];
                    dacc[i][j] += da[i]*bv[j] + a[i]*dbv[j];
                }
        }
        __syncthreads();
    }
#pragma unroll
    for (int i = 0; i < 4; i++) {
        int row = i0 + ty*4 + i;
#pragma unroll
        for (int j = 0; j < 4; j++) {
            int col = j0 + tx*4 + j;
            sb [(size_t)row*kS + col] = acc [i][j]*0.125f;
            dsb[(size_t)row*kS + col] = dacc[i][j]*0.125f;
        }
    }
}

// ---------------------------------------------------------------------------
// Softmax JVP (causal)
// ---------------------------------------------------------------------------
__global__ void softmax_jvp_kernel(float* __restrict__ sc, float* __restrict__ dsc)
{
    int i = blockIdx.x, bh = blockIdx.y;
    float* sr  = sc  + ((size_t)bh*kS + i)*kS;
    float* dsr = dsc + ((size_t)bh*kS + i)*kS;
    int len = i + 1;
    int t = threadIdx.x;  // 256
    __shared__ float shA[8], shB[8], bc[3];

    float mx = -1e30f;
    for (int j = t; j < len; j += 256) mx = fmaxf(mx, sr[j]);
#pragma unroll
    for (int o = 16; o > 0; o >>= 1) mx = fmaxf(mx, __shfl_xor_sync(0xffffffffu, mx, o));
    if ((t & 31) == 0) shA[t >> 5] = mx;
    __syncthreads();
    if (t < 32) {
        float r = (t < 8) ? shA[t] : -1e30f;
#pragma unroll
        for (int o = 4; o > 0; o >>= 1) r = fmaxf(r, __shfl_xor_sync(0xffffffffu, r, o));
        if (t == 0) bc[0] = r;
    }
    __syncthreads();
    mx = bc[0];
    __syncthreads();

    float Z = 0.f, T2 = 0.f;
    for (int j = t; j < len; j += 256) {
        float e = expf(sr[j] - mx);
        sr[j] = e;
        Z  += e;
        T2 += e * dsr[j];
    }
#pragma unroll
    for (int o = 16; o > 0; o >>= 1) {
        Z  += __shfl_xor_sync(0xffffffffu, Z , o);
        T2 += __shfl_xor_sync(0xffffffffu, T2, o);
    }
    if ((t & 31) == 0) { shA[t >> 5] = Z; shB[t >> 5] = T2; }
    __syncthreads();
    if (t < 32) {
        float a = (t < 8) ? shA[t] : 0.f;
        float b = (t < 8) ? shB[t] : 0.f;
#pragma unroll
        for (int o = 4; o > 0; o >>= 1) {
            a += __shfl_xor_sync(0xffffffffu, a, o);
            b += __shfl_xor_sync(0xffffffffu, b, o);
        }
        if (t == 0) { bc[1] = a; bc[2] = b; }
    }
    __syncthreads();
    float inv = 1.0f / bc[1];
    float sd  = bc[2] * inv;

    for (int j = t; j < len; j += 256) {
        float p = sr[j] * inv;
        sr[j]  = p;
        dsr[j] = p * (dsr[j] - sd);
    }
    int pad = ((i >> 6) + 1) << 6;
    if (pad > kS) pad = kS;
    for (int j = len + t; j < pad; j += 256) { sr[j] = 0.f; dsr[j] = 0.f; }
}

// ---------------------------------------------------------------------------
// AV JVP
// ---------------------------------------------------------------------------
__global__ void __launch_bounds__(256)
attn_o_kernel(const float* __restrict__ p, const float* __restrict__ dp,
              const float* __restrict__ v, const float* __restrict__ dv,
              float* __restrict__ o, float* __restrict__ dout)
{
    int it = blockIdx.x, bh = blockIdx.y;
    int b = bh >> 4, hh = bh & 15;
    const float* pb  = p  + (size_t)bh*kS*kS + (size_t)it*64*kS;
    const float* dpb = dp + (size_t)bh*kS*kS + (size_t)it*64*kS;
    size_t vbase = (size_t)b*kS*kD + (size_t)hh*kHD;
    const float* vb  = v  + vbase;
    const float* dvb = dv + vbase;
    float* ob  = o    + vbase + (size_t)it*64*kD;
    float* dob = dout + vbase + (size_t)it*64*kD;
    int Kend = (it + 1) * 64;

    __shared__ float Ps[16][64], dPs[16][64], Vs[16][64], dVs[16][64];
    int tid = threadIdx.x, tx = tid & 15, ty = tid >> 4;
    float acc[4][4], dacc[4][4];
#pragma unroll
    for (int i = 0; i < 4; i++)
#pragma unroll
        for (int j = 0; j < 4; j++) { acc[i][j] = 0.f; dacc[i][j] = 0.f; }

    for (int k0 = 0; k0 < Kend; k0 += 16) {
#pragma unroll
        for (int i = 0; i < 4; i++) {
            int idx = tid + i*256;
            {
                int rr = idx >> 4, cc = idx & 15;
                Ps [cc][rr] = pb [(size_t)rr*kS + k0 + cc];
                dPs[cc][rr] = dpb[(size_t)rr*kS + k0 + cc];
            }
            {
                int jj = idx >> 6, n = idx & 63;
                Vs [jj][n] = vb [(size_t)(k0+jj)*kD + n];
                dVs[jj][n] = dvb[(size_t)(k0+jj)*kD + n];
            }
        }
        __syncthreads();
#pragma unroll
        for (int d = 0; d < 16; d++) {
            float a[4], da[4], bv[4], dbv[4];
#pragma unroll
            for (int i = 0; i < 4; i++) { a[i] = Ps[d][ty*4+i]; da[i] = dPs[d][ty*4+i]; }
#pragma unroll
            for (int j = 0; j < 4; j++) { bv[j] = Vs[d][tx*4+j]; dbv[j] = dVs[d][tx*4+j]; }
#pragma unroll
            for (int i = 0; i < 4; i++)
#pragma unroll
                for (int j = 0; j < 4; j++) {
                    acc [i][j] += a[i]*bv[j];
                    dacc[i][j] += da[i]*bv[j] + a[i]*dbv[j];
                }
        }
        __syncthreads();
    }
#pragma unroll
    for (int i = 0; i < 4; i++) {
        int row = ty*4 + i;
#pragma unroll
        for (int j = 0; j < 4; j++) {
            int col = tx*4 + j;
            ob [(size_t)row*kD + col] = acc [i][j];
            dob[(size_t)row*kD + col] = dacc[i][j];
        }
    }
}

// ---------------------------------------------------------------------------
// GELU JVP
// ---------------------------------------------------------------------------
__global__ void gelu_jvp_kernel(float* __restrict__ u, float* __restrict__ du, int n)
{
    int i = blockIdx.x * 256 + threadIdx.x;
    if (i >= n) return;
    float x = u[i], dx = du[i];
    const float c = 0.7978845608028654f, a = 0.044715f;
    float x2 = x*x;
    float w  = c*(x + a*x*x2);
    float t  = tanhf(w);
    float g  = 0.5f*x*(1.f + t);
    float gp = 0.5f*(1.f + t) + 0.5f*x*(1.f - t*t)*c*(1.f + 3.f*a*x2);
    u[i]  = g;
    du[i] = gp*dx;
}

// ---------------------------------------------------------------------------
// Host orchestration
// ---------------------------------------------------------------------------
static inline void sgemm(const float* A, const float* B, float* C,
                         int M, int N, int K, int accum)
{
    dim3 grid(N/64, M/128);
    tf32gemm_kernel<<<grid, 256>>>(A, B, C, M, N, K, accum);
}

extern "C" void kernel_launch(void* const* d_in, const int* in_sizes, int n_in,
                              void* d_out, int out_size)
{
    (void)in_sizes; (void)n_in; (void)out_size;
    const int*   ids  = (const int*)  d_in[0];
    const float* emb  = (const float*)d_in[1];
    const float* Wq   = (const float*)d_in[2];
    const float* Wk   = (const float*)d_in[3];
    const float* Wv   = (const float*)d_in[4];
    const float* Wo   = (const float*)d_in[5];
    const float* W1   = (const float*)d_in[6];
    const float* W2   = (const float*)d_in[7];
    const float* ln1  = (const float*)d_in[8];
    const float* ln2  = (const float*)d_in[9];
    const float* lnf  = (const float*)d_in[10];
    const float* lmh  = (const float*)d_in[11];
    const float* Aq0  = (const float*)d_in[12];
    const float* Av0  = (const float*)d_in[14];
    const float* Bq   = (const float*)d_in[17];
    const float* Bv   = (const float*)d_in[19];
    float* out = (float*)d_out;

    float *x,*dx,*h,*dh,*q,*k,*v,*dq,*dk,*dv,*o,*dd,*u,*du,*sc,*dsc,*tt;
    cudaGetSymbolAddress((void**)&x,  g_x);
    cudaGetSymbolAddress((void**)&dx, g_dx);
    cudaGetSymbolAddress((void**)&h,  g_h);
    cudaGetSymbolAddress((void**)&dh, g_dh);
    cudaGetSymbolAddress((void**)&q,  g_q);
    cudaGetSymbolAddress((void**)&k,  g_k);
    cudaGetSymbolAddress((void**)&v,  g_v);
    cudaGetSymbolAddress((void**)&dq, g_dq);
    cudaGetSymbolAddress((void**)&dk, g_dk);
    cudaGetSymbolAddress((void**)&dv, g_dv);
    cudaGetSymbolAddress((void**)&o,  g_o);
    cudaGetSymbolAddress((void**)&dd, g_do);
    cudaGetSymbolAddress((void**)&u,  g_u);
    cudaGetSymbolAddress((void**)&du, g_du);
    cudaGetSymbolAddress((void**)&sc, g_sc);
    cudaGetSymbolAddress((void**)&dsc,g_dsc);
    cudaGetSymbolAddress((void**)&tt, g_t);

    embed_kernel<<<dim3(kD/256, kM), 256>>>(ids, emb, x, dx);

    for (int l = 0; l < kL; l++) {
        const float* Wq_l = Wq + (size_t)l*kD*kD;
        const float* Wk_l = Wk + (size_t)l*kD*kD;
        const float* Wv_l = Wv + (size_t)l*kD*kD;
        const float* Wo_l = Wo + (size_t)l*kD*kD;
        const float* W1_l = W1 + (size_t)l*kD*kFF;
        const float* W2_l = W2 + (size_t)l*kFF*kD;

        rms_jvp_kernel<<<kM, 256>>>(x, dx, ln1 + (size_t)l*kD, h, dh, 0);

        sgemm(h,  Wq_l, q,  kM, kD, kD, 0);
        sgemm(h,  Wk_l, k,  kM, kD, kD, 0);
        sgemm(h,  Wv_l, v,  kM, kD, kD, 0);
        sgemm(dh, Wq_l, dq, kM, kD, kD, 0);
        sgemm(dh, Wk_l, dk, kM, kD, kD, 0);
        sgemm(dh, Wv_l, dv, kM, kD, kD, 0);

        lora_t_kernel<<<dim3(kM, kR), 128>>>(h, Aq0 + (size_t)l*kR*kD, tt);
        lora_add_kernel<<<dim3(kD/256, kM), 256>>>(tt, Bq + (size_t)l*kD*kR, dq);
        lora_t_kernel<<<dim3(kM, kR), 128>>>(h, Av0 + (size_t)l*kR*kD, tt);
        lora_add_kernel<<<dim3(kD/256, kM), 256>>>(tt, Bv + (size_t)l*kD*kR, dv);

        attn_scores_kernel<<<dim3(kS/64, kS/64, kBH), 256>>>(q, k, dq, dk, sc, dsc);
        softmax_jvp_kernel<<<dim3(kS, kBH), 256>>>(sc, dsc);
        attn_o_kernel<<<dim3(kS/64, kBH), 256>>>(sc, dsc, v, dv, o, dd);

        sgemm(o,  Wo_l, x,  kM, kD, kD, 1);
        sgemm(dd, Wo_l, dx, kM, kD, kD, 1);

        rms_jvp_kernel<<<kM, 256>>>(x, dx, ln2 + (size_t)l*kD, h, dh, 0);
        sgemm(h,  W1_l, u,  kM, kFF, kD, 0);
        sgemm(dh, W1_l, du, kM, kFF, kD, 0);
        gelu_jvp_kernel<<<(kM*kFF)/256, 256>>>(u, du, kM*kFF);
        sgemm(u,  W2_l, x,  kM, kD, kFF, 1);
        sgemm(du, W2_l, dx, kM, kD, kFF, 1);
    }

    rms_jvp_kernel<<<kM, 256>>>(x, dx, lnf, h, h, 1);
    sgemm(h, lmh, out, kM, kV, kD, 0);
}

// round 8
// speedup vs baseline: 2.2414x; 2.2414x over previous
#include <cuda_runtime.h>
#include <math.h>
#include <stdint.h>

// Problem constants
#define kB   2
#define kS   1024
#define kD   1024
#define kH   16
#define kHD  64
#define kFF  4096
#define kV   32000
#define kR   16
#define kL   2
#define kM   2048          /* B*S */
#define kBH  32            /* B*H */
#define LORA_S 2.0f
#define RMS_EPS 1e-6f

// ---------------------------------------------------------------------------
// fp32 scratch
// ---------------------------------------------------------------------------
__device__ float g_x [kM*kD];
__device__ float g_dx[kM*kD];
__device__ float g_h [kM*kD];
__device__ float g_dh[kM*kD];
__device__ float g_q [kM*kD];
__device__ float g_k [kM*kD];
__device__ float g_v [kM*kD];
__device__ float g_dq[kM*kD];
__device__ float g_dk[kM*kD];
__device__ float g_dv[kM*kD];
__device__ float g_o [kM*kD];
__device__ float g_do[kM*kD];
__device__ float g_u [kM*kFF];
__device__ float g_du[kM*kFF];
__device__ float g_sc [kBH*kS*kS];
__device__ float g_dsc[kBH*kS*kS];
__device__ float g_t [kM*kR];

// tf32 hi/lo planes, fragment-permuted layouts
__device__ unsigned g_a1H[(size_t)kM*kFF];
__device__ unsigned g_a1L[(size_t)kM*kFF];
__device__ unsigned g_a2H[(size_t)kM*kFF];
__device__ unsigned g_a2L[(size_t)kM*kFF];

// weights: per layer [Wq|Wk|Wv|Wo|W1|W2], then lm_head
#define WLAYER (4*(size_t)kD*kD + 2*(size_t)kD*kFF)     /* 12582912 u32 */
#define WTOT   (kL*WLAYER + (size_t)kD*kV)
__device__ unsigned g_wH[WTOT];
__device__ unsigned g_wL[WTOT];

// ---------------------------------------------------------------------------
// helpers
// ---------------------------------------------------------------------------
__device__ __forceinline__ uint32_t smem_addr_u32(const void* p) {
    uint32_t a;
    asm("{ .reg .u64 t; cvta.to.shared.u64 t, %1; cvt.u32.u64 %0, t; }"
        : "=r"(a) : "l"(p));
    return a;
}
__device__ __forceinline__ void split2(float x, unsigned& h, unsigned& l) {
    asm("cvt.rna.tf32.f32 %0, %1;" : "=r"(h) : "f"(x));
    float r = x - __uint_as_float(h);
    asm("cvt.rna.tf32.f32 %0, %1;" : "=r"(l) : "f"(r));
}
__device__ __forceinline__ void mma8(float* c, uint4 a, uint2 b) {
    asm volatile(
        "mma.sync.aligned.m16n8k8.row.col.f32.tf32.tf32.f32 "
        "{%0,%1,%2,%3}, {%4,%5,%6,%7}, {%8,%9}, {%0,%1,%2,%3};"
        : "+f"(c[0]), "+f"(c[1]), "+f"(c[2]), "+f"(c[3])
        : "r"(a.x), "r"(a.y), "r"(a.z), "r"(a.w), "r"(b.x), "r"(b.y));
}

// ---------------------------------------------------------------------------
// Split pre-pass, A operand: [M,K] fp32 -> per (mtile 128, ktile 32) tiles of
// 4096 u32: quad q=((mfrag*4+kstep)*32+lane), regs (a0,a1,a2,a3) of m16n8k8.
// ---------------------------------------------------------------------------
__global__ void __launch_bounds__(256)
splitA_kernel(const float* __restrict__ src, unsigned* __restrict__ dH,
              unsigned* __restrict__ dL, int M, int K)
{
    __shared__ float ts[128*32];
    int mt = blockIdx.y, kt = blockIdx.x, tid = threadIdx.x;
    int KT = K >> 5;
    const float* sb = src + (size_t)mt*128*K + kt*32;
#pragma unroll
    for (int i = 0; i < 4; i++) {
        int q = tid + i*256;
        int r = q >> 3, c = (q & 7) << 2;
        float4 v = *reinterpret_cast<const float4*>(sb + (size_t)r*K + c);
        ts[r*32+c] = v.x; ts[r*32+c+1] = v.y; ts[r*32+c+2] = v.z; ts[r*32+c+3] = v.w;
    }
    __syncthreads();
    size_t tb = ((size_t)mt*KT + kt) * 4096;
#pragma unroll
    for (int i = 0; i < 4; i++) {
        int q = tid + i*256;               // quad 0..1023
        int lane = q & 31, kstep = (q >> 5) & 3, mfrag = q >> 7;
        int g = lane >> 2, t = lane & 3;
        int r0 = mfrag*16 + g, c0 = kstep*8 + t;
        float x0 = ts[r0*32 + c0];
        float x1 = ts[(r0+8)*32 + c0];
        float x2 = ts[r0*32 + c0 + 4];
        float x3 = ts[(r0+8)*32 + c0 + 4];
        unsigned h0,h1,h2,h3,l0,l1,l2,l3;
        split2(x0,h0,l0); split2(x1,h1,l1); split2(x2,h2,l2); split2(x3,h3,l3);
        *reinterpret_cast<uint4*>(dH + tb + (size_t)q*4) = make_uint4(h0,h1,h2,h3);
        *reinterpret_cast<uint4*>(dL + tb + (size_t)q*4) = make_uint4(l0,l1,l2,l3);
    }
}

// ---------------------------------------------------------------------------
// Split pre-pass, B operand: [K,N] fp32 -> per (ntile 128, ktile 32) tiles of
// 4096 u32: pair q=((nfrag*4+kstep)*32+lane), regs (b0,b1) of m16n8k8.
// ---------------------------------------------------------------------------
__global__ void __launch_bounds__(256)
splitB_kernel(const float* __restrict__ src, unsigned* __restrict__ dH,
              unsigned* __restrict__ dL, int K, int N)
{
    __shared__ float ts[32*128];
    int nt = blockIdx.x, kt = blockIdx.y, tid = threadIdx.x;
    int KT = K >> 5;
    const float* sb = src + (size_t)kt*32*N + (size_t)nt*128;
#pragma unroll
    for (int i = 0; i < 4; i++) {
        int q = tid + i*256;               // 1024 float4
        int r = q >> 5, c = (q & 31) << 2;
        float4 v = *reinterpret_cast<const float4*>(sb + (size_t)r*N + c);
        ts[r*128+c] = v.x; ts[r*128+c+1] = v.y; ts[r*128+c+2] = v.z; ts[r*128+c+3] = v.w;
    }
    __syncthreads();
    size_t tb = ((size_t)nt*KT + kt) * 4096;
#pragma unroll
    for (int i = 0; i < 8; i++) {
        int q = tid + i*256;               // pair 0..2047
        int lane = q & 31, kstep = (q >> 5) & 3, nfrag = q >> 7;
        int g = lane >> 2, t = lane & 3;
        int n = nfrag*8 + g, k0 = kstep*8;
        float x0 = ts[(k0+t)*128 + n];
        float x1 = ts[(k0+t+4)*128 + n];
        unsigned h0,h1,l0,l1;
        split2(x0,h0,l0); split2(x1,h1,l1);
        *reinterpret_cast<uint2*>(dH + tb + (size_t)q*2) = make_uint2(h0,h1);
        *reinterpret_cast<uint2*>(dL + tb + (size_t)q*2) = make_uint2(l0,l1);
    }
}

// ---------------------------------------------------------------------------
// 3xTF32 GEMM v2: C[M,N] (+)= A@B. BM=128 BN=128 BK=32, 8 warps (4m x 2n),
// warp tile 32x64. Fragment-permuted operands, cp.async 3-stage pipeline.
// ---------------------------------------------------------------------------
#define GSTAGE 16384u   /* u32 per stage: AH 4096 | AL 4096 | BH 4096 | BL 4096 */

__global__ void __launch_bounds__(256, 1)
tf32v2_kernel(const unsigned* __restrict__ AH, const unsigned* __restrict__ AL,
              const unsigned* __restrict__ BH, const unsigned* __restrict__ BL,
              float* __restrict__ C, int M, int N, int K, int accum)
{
    extern __shared__ unsigned smem[];       // 3 * GSTAGE u32
    int tid = threadIdx.x, lane = tid & 31, warp = tid >> 5;
    int wm = warp & 3, wn = warp >> 2;
    int nt = blockIdx.x, mt = blockIdx.y;
    int KT = K >> 5;
    const unsigned* aH = AH + (size_t)mt*KT*4096;
    const unsigned* aL = AL + (size_t)mt*KT*4096;
    const unsigned* bH = BH + (size_t)nt*KT*4096;
    const unsigned* bL = BL + (size_t)nt*KT*4096;
    uint32_t sbase = smem_addr_u32(smem);

    float c[2][8][4];
#pragma unroll
    for (int mf = 0; mf < 2; mf++)
#pragma unroll
        for (int nf = 0; nf < 8; nf++)
#pragma unroll
            for (int i = 0; i < 4; i++) c[mf][nf][i] = 0.f;

    auto fill = [&](int s, int j) {
#pragma unroll
        for (int i = 0; i < 16; i++) {
            int ch  = tid + i*256;           // 0..4095 16B chunks
            int rg  = ch >> 10;              // 0:AH 1:AL 2:BH 3:BL
            int off = (ch & 1023) * 4;       // u32 offset within region
            const unsigned* sp;
            if      (rg == 0) sp = aH + (size_t)j*4096 + off;
            else if (rg == 1) sp = aL + (size_t)j*4096 + off;
            else if (rg == 2) sp = bH + (size_t)j*4096 + off;
            else              sp = bL + (size_t)j*4096 + off;
            uint32_t dst = sbase + (s*GSTAGE + rg*4096u + off) * 4u;
            asm volatile("cp.async.cg.shared.global [%0], [%1], 16;" :: "r"(dst), "l"(sp));
        }
        asm volatile("cp.async.commit_group;" ::: "memory");
    };

    fill(0, 0); fill(1, 1); fill(2, 2);      // KT >= 32 always

    for (int j = 0; j < KT; j++) {
        int s = j % 3;
        asm volatile("cp.async.wait_group %0;" :: "n"(2) : "memory");
        __syncthreads();
        const uint4* A_Hs = (const uint4*)(smem + s*GSTAGE);
        const uint4* A_Ls = (const uint4*)(smem + s*GSTAGE + 4096);
        const uint2* B_Hs = (const uint2*)(smem + s*GSTAGE + 8192);
        const uint2* B_Ls = (const uint2*)(smem + s*GSTAGE + 12288);
#pragma unroll
        for (int ks = 0; ks < 4; ks++) {
            uint4 a0H = A_Hs[((wm*2+0)*4 + ks)*32 + lane];
            uint4 a1H = A_Hs[((wm*2+1)*4 + ks)*32 + lane];
            uint4 a0L = A_Ls[((wm*2+0)*4 + ks)*32 + lane];
            uint4 a1L = A_Ls[((wm*2+1)*4 + ks)*32 + lane];
#pragma unroll
            for (int nf = 0; nf < 8; nf++) {
                int bi = ((wn*8 + nf)*4 + ks)*32 + lane;
                uint2 bh = B_Hs[bi];
                uint2 bl = B_Ls[bi];
                mma8(c[0][nf], a0H, bh);
                mma8(c[1][nf], a1H, bh);
                mma8(c[0][nf], a0H, bl);
                mma8(c[1][nf], a1H, bl);
                mma8(c[0][nf], a0L, bh);
                mma8(c[1][nf], a1L, bh);
            }
        }
        __syncthreads();
        if (j + 3 < KT) fill(s, j + 3);
        else asm volatile("cp.async.commit_group;" ::: "memory");
    }

    int g = lane >> 2, t = lane & 3;
#pragma unroll
    for (int mf = 0; mf < 2; mf++) {
#pragma unroll
        for (int nf = 0; nf < 8; nf++) {
            int r  = mt*128 + wm*32 + mf*16 + g;
            int cc = nt*128 + wn*64 + nf*8 + 2*t;
            float* p0 = C + (size_t)r*N + cc;
            float* p1 = C + (size_t)(r+8)*N + cc;
            float2 v0 = make_float2(c[mf][nf][0], c[mf][nf][1]);
            float2 v1 = make_float2(c[mf][nf][2], c[mf][nf][3]);
            if (accum) {
                float2 o0 = *reinterpret_cast<float2*>(p0);
                float2 o1 = *reinterpret_cast<float2*>(p1);
                v0.x += o0.x; v0.y += o0.y; v1.x += o1.x; v1.y += o1.y;
            }
            *reinterpret_cast<float2*>(p0) = v0;
            *reinterpret_cast<float2*>(p1) = v1;
        }
    }
}

// ---------------------------------------------------------------------------
// Non-GEMM kernels (proven in round 1)
// ---------------------------------------------------------------------------
__global__ void embed_kernel(const int* __restrict__ ids,
                             const float* __restrict__ emb,
                             float* __restrict__ x, float* __restrict__ dx)
{
    int m = blockIdx.y;
    int d = blockIdx.x * 256 + threadIdx.x;
    int id = ids[m];
    x [(size_t)m*kD + d] = emb[(size_t)id*kD + d];
    dx[(size_t)m*kD + d] = 0.0f;
}

__global__ void rms_jvp_kernel(const float* __restrict__ x,
                               const float* __restrict__ dx,
                               const float* __restrict__ g,
                               float* __restrict__ h, float* __restrict__ dh,
                               int sum_mode)
{
    int m = blockIdx.x;
    const float* xr  = x  + (size_t)m*kD;
    const float* dxr = dx + (size_t)m*kD;
    int t = threadIdx.x;   // 256
    float xv[4], dv[4];
    float s2 = 0.f, sxd = 0.f;
#pragma unroll
    for (int i = 0; i < 4; i++) {
        int d = t + i*256;
        xv[i] = xr[d]; dv[i] = dxr[d];
        s2  += xv[i]*xv[i];
        sxd += xv[i]*dv[i];
    }
    __shared__ float shA[8], shB[8], bc[2];
#pragma unroll
    for (int o = 16; o > 0; o >>= 1) {
        s2  += __shfl_xor_sync(0xffffffffu, s2 , o);
        sxd += __shfl_xor_sync(0xffffffffu, sxd, o);
    }
    int w = t >> 5;
    if ((t & 31) == 0) { shA[w] = s2; shB[w] = sxd; }
    __syncthreads();
    if (t < 32) {
        float a = (t < 8) ? shA[t] : 0.f;
        float b = (t < 8) ? shB[t] : 0.f;
#pragma unroll
        for (int o = 4; o > 0; o >>= 1) {
            a += __shfl_xor_sync(0xffffffffu, a, o);
            b += __shfl_xor_sync(0xffffffffu, b, o);
        }
        if (t == 0) { bc[0] = a; bc[1] = b; }
    }
    __syncthreads();
    float m2 = bc[0] * (1.0f/kD) + RMS_EPS;
    float n  = 1.0f / sqrtf(m2);
    float c  = (bc[1] * (1.0f/kD)) / m2;
#pragma unroll
    for (int i = 0; i < 4; i++) {
        int d = t + i*256;
        float gv = g[d];
        if (sum_mode) {
            h[(size_t)m*kD + d] = gv*n*(xv[i] + dv[i] - xv[i]*c);
        } else {
            h [(size_t)m*kD + d] = gv*n*xv[i];
            dh[(size_t)m*kD + d] = gv*n*(dv[i] - xv[i]*c);
        }
    }
}

__global__ void lora_t_kernel(const float* __restrict__ h,
                              const float* __restrict__ A0,
                              float* __restrict__ T)
{
    int m = blockIdx.x, r = blockIdx.y;
    const float* hr = h  + (size_t)m*kD;
    const float* ar = A0 + (size_t)r*kD;
    float s = 0.f;
    for (int d = threadIdx.x; d < kD; d += 128) s += hr[d]*ar[d];
#pragma unroll
    for (int o = 16; o > 0; o >>= 1) s += __shfl_xor_sync(0xffffffffu, s, o);
    __shared__ float sh[4];
    if ((threadIdx.x & 31) == 0) sh[threadIdx.x >> 5] = s;
    __syncthreads();
    if (threadIdx.x == 0) T[(size_t)m*kR + r] = sh[0]+sh[1]+sh[2]+sh[3];
}

__global__ void lora_add_kernel(const float* __restrict__ T,
                                const float* __restrict__ Bm,
                                float* __restrict__ dq)
{
    int m = blockIdx.y;
    int n = blockIdx.x * 256 + threadIdx.x;
    __shared__ float ts[kR];
    if (threadIdx.x < kR) ts[threadIdx.x] = T[(size_t)m*kR + threadIdx.x];
    __syncthreads();
    float s = 0.f;
#pragma unroll
    for (int r = 0; r < kR; r++) s += ts[r]*Bm[(size_t)n*kR + r];
    dq[(size_t)m*kD + n] += LORA_S * s;
}

__global__ void __launch_bounds__(256)
attn_scores_kernel(const float* __restrict__ q, const float* __restrict__ k,
                   const float* __restrict__ dq, const float* __restrict__ dk,
                   float* __restrict__ sc, float* __restrict__ dsc)
{
    int jt = blockIdx.x, it = blockIdx.y, bh = blockIdx.z;
    if (jt > it) return;
    int b = bh >> 4, hh = bh & 15;
    size_t bse = (size_t)b*kS*kD + (size_t)hh*kHD;
    const float* qb  = q  + bse;
    const float* kb  = k  + bse;
    const float* dqb = dq + bse;
    const float* dkb = dk + bse;
    float* sb  = sc  + (size_t)bh*kS*kS;
    float* dsb = dsc + (size_t)bh*kS*kS;
    int i0 = it*64, j0 = jt*64;

    __shared__ float Qs[16][64], dQs[16][64], Ks[16][64], dKs[16][64];
    int tid = threadIdx.x, tx = tid & 15, ty = tid >> 4;
    float acc[4][4], dacc[4][4];
#pragma unroll
    for (int i = 0; i < 4; i++)
#pragma unroll
        for (int j = 0; j < 4; j++) { acc[i][j] = 0.f; dacc[i][j] = 0.f; }

    for (int kc = 0; kc < kHD; kc += 16) {
#pragma unroll
        for (int i = 0; i < 4; i++) {
            int idx = tid + i*256;
            int rr = idx >> 4, cc = idx & 15;
            Qs [cc][rr] = qb [(size_t)(i0+rr)*kD + kc + cc];
            dQs[cc][rr] = dqb[(size_t)(i0+rr)*kD + kc + cc];
            Ks [cc][rr] = kb [(size_t)(j0+rr)*kD + kc + cc];
            dKs[cc][rr] = dkb[(size_t)(j0+rr)*kD + kc + cc];
        }
        __syncthreads();
#pragma unroll
        for (int d = 0; d < 16; d++) {
            float a[4], da[4], bv[4], dbv[4];
#pragma unroll
            for (int i = 0; i < 4; i++) { a[i] = Qs[d][ty*4+i]; da[i] = dQs[d][ty*4+i]; }
#pragma unroll
            for (int j = 0; j < 4; j++) { bv[j] = Ks[d][tx*4+j]; dbv[j] = dKs[d][tx*4+j]; }
#pragma unroll
            for (int i = 0; i < 4; i++)
#pragma unroll
                for (int j = 0; j < 4; j++) {
                    acc [i][j] += a[i]*bv[j];
                    dacc[i][j] += da[i]*bv[j] + a[i]*dbv[j];
                }
        }
        __syncthreads();
    }
#pragma unroll
    for (int i = 0; i < 4; i++) {
        int row = i0 + ty*4 + i;
#pragma unroll
        for (int j = 0; j < 4; j++) {
            int col = j0 + tx*4 + j;
            sb [(size_t)row*kS + col] = acc [i][j]*0.125f;
            dsb[(size_t)row*kS + col] = dacc[i][j]*0.125f;
        }
    }
}

__global__ void softmax_jvp_kernel(float* __restrict__ sc, float* __restrict__ dsc)
{
    int i = blockIdx.x, bh = blockIdx.y;
    float* sr  = sc  + ((size_t)bh*kS + i)*kS;
    float* dsr = dsc + ((size_t)bh*kS + i)*kS;
    int len = i + 1;
    int t = threadIdx.x;  // 256
    __shared__ float shA[8], shB[8], bc[3];

    float mx = -1e30f;
    for (int j = t; j < len; j += 256) mx = fmaxf(mx, sr[j]);
#pragma unroll
    for (int o = 16; o > 0; o >>= 1) mx = fmaxf(mx, __shfl_xor_sync(0xffffffffu, mx, o));
    if ((t & 31) == 0) shA[t >> 5] = mx;
    __syncthreads();
    if (t < 32) {
        float r = (t < 8) ? shA[t] : -1e30f;
#pragma unroll
        for (int o = 4; o > 0; o >>= 1) r = fmaxf(r, __shfl_xor_sync(0xffffffffu, r, o));
        if (t == 0) bc[0] = r;
    }
    __syncthreads();
    mx = bc[0];
    __syncthreads();

    float Z = 0.f, T2 = 0.f;
    for (int j = t; j < len; j += 256) {
        float e = expf(sr[j] - mx);
        sr[j] = e;
        Z  += e;
        T2 += e * dsr[j];
    }
#pragma unroll
    for (int o = 16; o > 0; o >>= 1) {
        Z  += __shfl_xor_sync(0xffffffffu, Z , o);
        T2 += __shfl_xor_sync(0xffffffffu, T2, o);
    }
    if ((t & 31) == 0) { shA[t >> 5] = Z; shB[t >> 5] = T2; }
    __syncthreads();
    if (t < 32) {
        float a = (t < 8) ? shA[t] : 0.f;
        float b = (t < 8) ? shB[t] : 0.f;
#pragma unroll
        for (int o = 4; o > 0; o >>= 1) {
            a += __shfl_xor_sync(0xffffffffu, a, o);
            b += __shfl_xor_sync(0xffffffffu, b, o);
        }
        if (t == 0) { bc[1] = a; bc[2] = b; }
    }
    __syncthreads();
    float inv = 1.0f / bc[1];
    float sd  = bc[2] * inv;

    for (int j = t; j < len; j += 256) {
        float p = sr[j] * inv;
        sr[j]  = p;
        dsr[j] = p * (dsr[j] - sd);
    }
    int pad = ((i >> 6) + 1) << 6;
    if (pad > kS) pad = kS;
    for (int j = len + t; j < pad; j += 256) { sr[j] = 0.f; dsr[j] = 0.f; }
}

__global__ void __launch_bounds__(256)
attn_o_kernel(const float* __restrict__ p, const float* __restrict__ dp,
              const float* __restrict__ v, const float* __restrict__ dv,
              float* __restrict__ o, float* __restrict__ dout)
{
    int it = blockIdx.x, bh = blockIdx.y;
    int b = bh >> 4, hh = bh & 15;
    const float* pb  = p  + (size_t)bh*kS*kS + (size_t)it*64*kS;
    const float* dpb = dp + (size_t)bh*kS*kS + (size_t)it*64*kS;
    size_t vbase = (size_t)b*kS*kD + (size_t)hh*kHD;
    const float* vb  = v  + vbase;
    const float* dvb = dv + vbase;
    float* ob  = o    + vbase + (size_t)it*64*kD;
    float* dob = dout + vbase + (size_t)it*64*kD;
    int Kend = (it + 1) * 64;

    __shared__ float Ps[16][64], dPs[16][64], Vs[16][64], dVs[16][64];
    int tid = threadIdx.x, tx = tid & 15, ty = tid >> 4;
    float acc[4][4], dacc[4][4];
#pragma unroll
    for (int i = 0; i < 4; i++)
#pragma unroll
        for (int j = 0; j < 4; j++) { acc[i][j] = 0.f; dacc[i][j] = 0.f; }

    for (int k0 = 0; k0 < Kend; k0 += 16) {
#pragma unroll
        for (int i = 0; i < 4; i++) {
            int idx = tid + i*256;
            {
                int rr = idx >> 4, cc = idx & 15;
                Ps [cc][rr] = pb [(size_t)rr*kS + k0 + cc];
                dPs[cc][rr] = dpb[(size_t)rr*kS + k0 + cc];
            }
            {
                int jj = idx >> 6, n = idx & 63;
                Vs [jj][n] = vb [(size_t)(k0+jj)*kD + n];
                dVs[jj][n] = dvb[(size_t)(k0+jj)*kD + n];
            }
        }
        __syncthreads();
#pragma unroll
        for (int d = 0; d < 16; d++) {
            float a[4], da[4], bv[4], dbv[4];
#pragma unroll
            for (int i = 0; i < 4; i++) { a[i] = Ps[d][ty*4+i]; da[i] = dPs[d][ty*4+i]; }
#pragma unroll
            for (int j = 0; j < 4; j++) { bv[j] = Vs[d][tx*4+j]; dbv[j] = dVs[d][tx*4+j]; }
#pragma unroll
            for (int i = 0; i < 4; i++)
#pragma unroll
                for (int j = 0; j < 4; j++) {
                    acc [i][j] += a[i]*bv[j];
                    dacc[i][j] += da[i]*bv[j] + a[i]*dbv[j];
                }
        }
        __syncthreads();
    }
#pragma unroll
    for (int i = 0; i < 4; i++) {
        int row = ty*4 + i;
#pragma unroll
        for (int j = 0; j < 4; j++) {
            int col = tx*4 + j;
            ob [(size_t)row*kD + col] = acc [i][j];
            dob[(size_t)row*kD + col] = dacc[i][j];
        }
    }
}

__global__ void gelu_jvp_kernel(float* __restrict__ u, float* __restrict__ du, int n)
{
    int i = blockIdx.x * 256 + threadIdx.x;
    if (i >= n) return;
    float x = u[i], dx = du[i];
    const float c = 0.7978845608028654f, a = 0.044715f;
    float x2 = x*x;
    float w  = c*(x + a*x*x2);
    float t  = tanhf(w);
    float g  = 0.5f*x*(1.f + t);
    float gp = 0.5f*(1.f + t) + 0.5f*x*(1.f - t*t)*c*(1.f + 3.f*a*x2);
    u[i]  = g;
    du[i] = gp*dx;
}

// ---------------------------------------------------------------------------
// Host orchestration
// ---------------------------------------------------------------------------
static void splitA(const float* src, unsigned* dH, unsigned* dL, int M, int K) {
    splitA_kernel<<<dim3(K/32, M/128), 256>>>(src, dH, dL, M, K);
}
static void splitB(const float* src, unsigned* dH, unsigned* dL, int K, int N) {
    splitB_kernel<<<dim3(N/128, K/32), 256>>>(src, dH, dL, K, N);
}
static void tfgemm(const unsigned* aH, const unsigned* aL,
                   const unsigned* bH, const unsigned* bL,
                   float* C, int M, int N, int K, int accum) {
    tf32v2_kernel<<<dim3(N/128, M/128), 256, 3*GSTAGE*4>>>(aH, aL, bH, bL, C, M, N, K, accum);
}

extern "C" void kernel_launch(void* const* d_in, const int* in_sizes, int n_in,
                              void* d_out, int out_size)
{
    (void)in_sizes; (void)n_in; (void)out_size;
    const int*   ids  = (const int*)  d_in[0];
    const float* emb  = (const float*)d_in[1];
    const float* Wq   = (const float*)d_in[2];
    const float* Wk   = (const float*)d_in[3];
    const float* Wv   = (const float*)d_in[4];
    const float* Wo   = (const float*)d_in[5];
    const float* W1   = (const float*)d_in[6];
    const float* W2   = (const float*)d_in[7];
    const float* ln1  = (const float*)d_in[8];
    const float* ln2  = (const float*)d_in[9];
    const float* lnf  = (const float*)d_in[10];
    const float* lmh  = (const float*)d_in[11];
    const float* Aq0  = (const float*)d_in[12];
    const float* Av0  = (const float*)d_in[14];
    const float* Bq   = (const float*)d_in[17];
    const float* Bv   = (const float*)d_in[19];
    float* out = (float*)d_out;

    cudaFuncSetAttribute(tf32v2_kernel,
                         cudaFuncAttributeMaxDynamicSharedMemorySize, 3*GSTAGE*4);

    float *x,*dx,*h,*dh,*q,*k,*v,*dq,*dk,*dv,*o,*dd,*u,*du,*sc,*dsc,*tt;
    cudaGetSymbolAddress((void**)&x,  g_x);
    cudaGetSymbolAddress((void**)&dx, g_dx);
    cudaGetSymbolAddress((void**)&h,  g_h);
    cudaGetSymbolAddress((void**)&dh, g_dh);
    cudaGetSymbolAddress((void**)&q,  g_q);
    cudaGetSymbolAddress((void**)&k,  g_k);
    cudaGetSymbolAddress((void**)&v,  g_v);
    cudaGetSymbolAddress((void**)&dq, g_dq);
    cudaGetSymbolAddress((void**)&dk, g_dk);
    cudaGetSymbolAddress((void**)&dv, g_dv);
    cudaGetSymbolAddress((void**)&o,  g_o);
    cudaGetSymbolAddress((void**)&dd, g_do);
    cudaGetSymbolAddress((void**)&u,  g_u);
    cudaGetSymbolAddress((void**)&du, g_du);
    cudaGetSymbolAddress((void**)&sc, g_sc);
    cudaGetSymbolAddress((void**)&dsc,g_dsc);
    cudaGetSymbolAddress((void**)&tt, g_t);

    unsigned *a1H,*a1L,*a2H,*a2L,*wH,*wL;
    cudaGetSymbolAddress((void**)&a1H, g_a1H);
    cudaGetSymbolAddress((void**)&a1L, g_a1L);
    cudaGetSymbolAddress((void**)&a2H, g_a2H);
    cudaGetSymbolAddress((void**)&a2L, g_a2L);
    cudaGetSymbolAddress((void**)&wH,  g_wH);
    cudaGetSymbolAddress((void**)&wL,  g_wL);

    // weight splits
    const size_t DD = (size_t)kD*kD, DF = (size_t)kD*kFF;
    for (int l = 0; l < kL; l++) {
        size_t b0 = (size_t)l * WLAYER;
        splitB(Wq + (size_t)l*DD, wH + b0,          wL + b0,          kD, kD);
        splitB(Wk + (size_t)l*DD, wH + b0 + DD,     wL + b0 + DD,     kD, kD);
        splitB(Wv + (size_t)l*DD, wH + b0 + 2*DD,   wL + b0 + 2*DD,   kD, kD);
        splitB(Wo + (size_t)l*DD, wH + b0 + 3*DD,   wL + b0 + 3*DD,   kD, kD);
        splitB(W1 + (size_t)l*DF, wH + b0 + 4*DD,   wL + b0 + 4*DD,   kD, kFF);
        splitB(W2 + (size_t)l*DF, wH + b0 + 4*DD+DF, wL + b0 + 4*DD+DF, kFF, kD);
    }
    size_t lmOff = (size_t)kL * WLAYER;
    splitB(lmh, wH + lmOff, wL + lmOff, kD, kV);

    embed_kernel<<<dim3(kD/256, kM), 256>>>(ids, emb, x, dx);

    for (int l = 0; l < kL; l++) {
        size_t b0 = (size_t)l * WLAYER;
        const unsigned *wqH = wH + b0,          *wqL = wL + b0;
        const unsigned *wkH = wH + b0 + DD,     *wkL = wL + b0 + DD;
        const unsigned *wvH = wH + b0 + 2*DD,   *wvL = wL + b0 + 2*DD;
        const unsigned *woH = wH + b0 + 3*DD,   *woL = wL + b0 + 3*DD;
        const unsigned *w1H = wH + b0 + 4*DD,   *w1L = wL + b0 + 4*DD;
        const unsigned *w2H = wH + b0 + 4*DD+DF,*w2L = wL + b0 + 4*DD+DF;

        rms_jvp_kernel<<<kM, 256>>>(x, dx, ln1 + (size_t)l*kD, h, dh, 0);
        splitA(h,  a1H, a1L, kM, kD);
        splitA(dh, a2H, a2L, kM, kD);

        tfgemm(a1H, a1L, wqH, wqL, q,  kM, kD, kD, 0);
        tfgemm(a1H, a1L, wkH, wkL, k,  kM, kD, kD, 0);
        tfgemm(a1H, a1L, wvH, wvL, v,  kM, kD, kD, 0);
        tfgemm(a2H, a2L, wqH, wqL, dq, kM, kD, kD, 0);
        tfgemm(a2H, a2L, wkH, wkL, dk, kM, kD, kD, 0);
        tfgemm(a2H, a2L, wvH, wvL, dv, kM, kD, kD, 0);

        lora_t_kernel<<<dim3(kM, kR), 128>>>(h, Aq0 + (size_t)l*kR*kD, tt);
        lora_add_kernel<<<dim3(kD/256, kM), 256>>>(tt, Bq + (size_t)l*kD*kR, dq);
        lora_t_kernel<<<dim3(kM, kR), 128>>>(h, Av0 + (size_t)l*kR*kD, tt);
        lora_add_kernel<<<dim3(kD/256, kM), 256>>>(tt, Bv + (size_t)l*kD*kR, dv);

        attn_scores_kernel<<<dim3(kS/64, kS/64, kBH), 256>>>(q, k, dq, dk, sc, dsc);
        softmax_jvp_kernel<<<dim3(kS, kBH), 256>>>(sc, dsc);
        attn_o_kernel<<<dim3(kS/64, kBH), 256>>>(sc, dsc, v, dv, o, dd);

        splitA(o,  a1H, a1L, kM, kD);
        splitA(dd, a2H, a2L, kM, kD);
        tfgemm(a1H, a1L, woH, woL, x,  kM, kD, kD, 1);
        tfgemm(a2H, a2L, woH, woL, dx, kM, kD, kD, 1);

        rms_jvp_kernel<<<kM, 256>>>(x, dx, ln2 + (size_t)l*kD, h, dh, 0);
        splitA(h,  a1H, a1L, kM, kD);
        splitA(dh, a2H, a2L, kM, kD);
        tfgemm(a1H, a1L, w1H, w1L, u,  kM, kFF, kD, 0);
        tfgemm(a2H, a2L, w1H, w1L, du, kM, kFF, kD, 0);
        gelu_jvp_kernel<<<(kM*kFF)/256, 256>>>(u, du, kM*kFF);
        splitA(u,  a1H, a1L, kM, kFF);
        splitA(du, a2H, a2L, kM, kFF);
        tfgemm(a1H, a1L, w2H, w2L, x,  kM, kD, kFF, 1);
        tfgemm(a2H, a2L, w2H, w2L, dx, kM, kD, kFF, 1);
    }

    rms_jvp_kernel<<<kM, 256>>>(x, dx, lnf, h, h, 1);
    splitA(h, a1H, a1L, kM, kD);
    tfgemm(a1H, a1L, wH + lmOff, wL + lmOff, out, kM, kV, kD, 0);
}

// round 9
// speedup vs baseline: 3.3676x; 1.5025x over previous
#include <cuda_runtime.h>
#include <cuda_fp16.h>
#include <math.h>
#include <stdint.h>

// Problem constants
#define kB   2
#define kS   1024
#define kD   1024
#define kH   16
#define kHD  64
#define kFF  4096
#define kV   32000
#define kR   16
#define kL   2
#define kM   2048          /* B*S */
#define kBH  32            /* B*H */
#define LORA_S 2.0f
#define RMS_EPS 1e-6f

// ---------------------------------------------------------------------------
// fp32 scratch
// ---------------------------------------------------------------------------
__device__ float g_x [kM*kD];
__device__ float g_dx[kM*kD];
__device__ float g_h [kM*kD];
__device__ float g_dh[kM*kD];
__device__ float g_q [kM*kD];
__device__ float g_k [kM*kD];
__device__ float g_v [kM*kD];
__device__ float g_dq[kM*kD];
__device__ float g_dk[kM*kD];
__device__ float g_dv[kM*kD];
__device__ float g_o [kM*kD];
__device__ float g_do[kM*kD];
__device__ float g_u [kM*kFF];
__device__ float g_du[kM*kFF];
__device__ float g_sc [kBH*kS*kS];
__device__ float g_dsc[kBH*kS*kS];
__device__ float g_t [kM*kR];

// fp16 hi/lo planes (2 fp16 packed per u32), fragment-permuted for m16n8k16
__device__ unsigned g_a1H[(size_t)kM*kFF/2];
__device__ unsigned g_a1L[(size_t)kM*kFF/2];
__device__ unsigned g_a2H[(size_t)kM*kFF/2];
__device__ unsigned g_a2L[(size_t)kM*kFF/2];

// weights (u32 counts; each u32 = 2 fp16)
#define DD2 ((size_t)kD*kD/2)
#define DF2 ((size_t)kD*kFF/2)
#define WLAYER2 (4*DD2 + 2*DF2)
#define LM2 ((size_t)kD*kV/2)
#define WTOT2 (kL*WLAYER2 + LM2)
__device__ unsigned g_wH[WTOT2];
__device__ unsigned g_wL[WTOT2];

// ---------------------------------------------------------------------------
// helpers
// ---------------------------------------------------------------------------
__device__ __forceinline__ uint32_t smem_addr_u32(const void* p) {
    uint32_t a;
    asm("{ .reg .u64 t; cvta.to.shared.u64 t, %1; cvt.u32.u64 %0, t; }"
        : "=r"(a) : "l"(p));
    return a;
}
// split (x,y) into packed fp16 hi pair and fp16 lo (residual) pair
__device__ __forceinline__ void split_pack(float x, float y, unsigned& H, unsigned& L) {
    __half hx = __float2half_rn(x), hy = __float2half_rn(y);
    float rx = x - __half2float(hx), ry = y - __half2float(hy);
    __half lx = __float2half_rn(rx), ly = __float2half_rn(ry);
    __half2 Hh = __halves2half2(hx, hy);
    __half2 Ll = __halves2half2(lx, ly);
    H = *reinterpret_cast<unsigned*>(&Hh);
    L = *reinterpret_cast<unsigned*>(&Ll);
}
__device__ __forceinline__ void mma16(float* c, uint4 a, uint2 b) {
    asm volatile(
        "mma.sync.aligned.m16n8k16.row.col.f32.f16.f16.f32 "
        "{%0,%1,%2,%3}, {%4,%5,%6,%7}, {%8,%9}, {%0,%1,%2,%3};"
        : "+f"(c[0]), "+f"(c[1]), "+f"(c[2]), "+f"(c[3])
        : "r"(a.x), "r"(a.y), "r"(a.z), "r"(a.w), "r"(b.x), "r"(b.y));
}

// ---------------------------------------------------------------------------
// Split pre-pass, A operand: [M,K] fp32 -> per (mtile 128, ktile 64) tiles of
// 4096 u32/plane: quad q=((mfrag*4+kstep)*32+lane) -> uint4 (a0..a3) of
// m16n8k16 (each u32 = 2 fp16 along k).
// ---------------------------------------------------------------------------
__global__ void __launch_bounds__(256)
splitA16_kernel(const float* __restrict__ src, unsigned* __restrict__ dH,
                unsigned* __restrict__ dL, int M, int K)
{
    __shared__ float ts[128*64];
    int mt = blockIdx.y, kt = blockIdx.x, tid = threadIdx.x;
    int KT = K >> 6;
    const float* sb = src + (size_t)mt*128*K + kt*64;
#pragma unroll
    for (int i = 0; i < 8; i++) {
        int q = tid + i*256;                 // 2048 float4
        int r = q >> 4, c = (q & 15) << 2;
        float4 v = *reinterpret_cast<const float4*>(sb + (size_t)r*K + c);
        ts[r*64+c] = v.x; ts[r*64+c+1] = v.y; ts[r*64+c+2] = v.z; ts[r*64+c+3] = v.w;
    }
    __syncthreads();
    size_t tb = ((size_t)mt*KT + kt) * 4096;
#pragma unroll
    for (int i = 0; i < 4; i++) {
        int q = tid + i*256;                 // quad 0..1023
        int lane = q & 31, kstep = (q >> 5) & 3, mfrag = q >> 7;
        int g = lane >> 2, t = lane & 3;
        int r0 = mfrag*16 + g, c0 = kstep*16 + 2*t;
        unsigned h0,h1,h2,h3,l0,l1,l2,l3;
        split_pack(ts[r0*64+c0],       ts[r0*64+c0+1],       h0, l0);
        split_pack(ts[(r0+8)*64+c0],   ts[(r0+8)*64+c0+1],   h1, l1);
        split_pack(ts[r0*64+c0+8],     ts[r0*64+c0+9],       h2, l2);
        split_pack(ts[(r0+8)*64+c0+8], ts[(r0+8)*64+c0+9],   h3, l3);
        *reinterpret_cast<uint4*>(dH + tb + (size_t)q*4) = make_uint4(h0,h1,h2,h3);
        *reinterpret_cast<uint4*>(dL + tb + (size_t)q*4) = make_uint4(l0,l1,l2,l3);
    }
}

// ---------------------------------------------------------------------------
// Split pre-pass, B operand: [K,N] fp32 -> per (ntile 128, ktile 64) tiles of
// 4096 u32/plane: pair q=((nfrag*4+kstep)*32+lane) -> uint2 (b0,b1).
// ---------------------------------------------------------------------------
__global__ void __launch_bounds__(256)
splitB16_kernel(const float* __restrict__ src, unsigned* __restrict__ dH,
                unsigned* __restrict__ dL, int K, int N)
{
    __shared__ float ts[64*128];
    int nt = blockIdx.x, kt = blockIdx.y, tid = threadIdx.x;
    int KT = K >> 6;
    const float* sb = src + (size_t)kt*64*N + (size_t)nt*128;
#pragma unroll
    for (int i = 0; i < 8; i++) {
        int q = tid + i*256;                 // 2048 float4
        int r = q >> 5, c = (q & 31) << 2;
        float4 v = *reinterpret_cast<const float4*>(sb + (size_t)r*N + c);
        ts[r*128+c] = v.x; ts[r*128+c+1] = v.y; ts[r*128+c+2] = v.z; ts[r*128+c+3] = v.w;
    }
    __syncthreads();
    size_t tb = ((size_t)nt*KT + kt) * 4096;
#pragma unroll
    for (int i = 0; i < 8; i++) {
        int q = tid + i*256;                 // pair 0..2047
        int lane = q & 31, kstep = (q >> 5) & 3, nfrag = q >> 7;
        int g = lane >> 2, t = lane & 3;
        int n = nfrag*8 + g, k0 = kstep*16;
        unsigned h0,h1,l0,l1;
        split_pack(ts[(k0+2*t)*128+n],   ts[(k0+2*t+1)*128+n], h0, l0);
        split_pack(ts[(k0+2*t+8)*128+n], ts[(k0+2*t+9)*128+n], h1, l1);
        *reinterpret_cast<uint2*>(dH + tb + (size_t)q*2) = make_uint2(h0,h1);
        *reinterpret_cast<uint2*>(dL + tb + (size_t)q*2) = make_uint2(l0,l1);
    }
}

// ---------------------------------------------------------------------------
// 3xFP16 GEMM: C[M,N] (+)= A@B. BM=128 BN=128 BK=64, 8 warps (4m x 2n),
// warp tile 32x64, m16n8k16, cp.async 3-stage pipeline (192 KB smem).
// ---------------------------------------------------------------------------
#define GSTAGE 16384u   /* u32 per stage: AH 4096 | AL 4096 | BH 4096 | BL 4096 */

__global__ void __launch_bounds__(256, 1)
hgemm3_kernel(const unsigned* __restrict__ AH, const unsigned* __restrict__ AL,
              const unsigned* __restrict__ BH, const unsigned* __restrict__ BL,
              float* __restrict__ C, int M, int N, int K, int accum)
{
    extern __shared__ unsigned smem[];       // 3 * GSTAGE u32
    int tid = threadIdx.x, lane = tid & 31, warp = tid >> 5;
    int wm = warp & 3, wn = warp >> 2;
    int nt = blockIdx.x, mt = blockIdx.y;
    int KT = K >> 6;
    const unsigned* aH = AH + (size_t)mt*KT*4096;
    const unsigned* aL = AL + (size_t)mt*KT*4096;
    const unsigned* bH = BH + (size_t)nt*KT*4096;
    const unsigned* bL = BL + (size_t)nt*KT*4096;
    uint32_t sbase = smem_addr_u32(smem);

    float c[2][8][4];
#pragma unroll
    for (int mf = 0; mf < 2; mf++)
#pragma unroll
        for (int nf = 0; nf < 8; nf++)
#pragma unroll
            for (int i = 0; i < 4; i++) c[mf][nf][i] = 0.f;

    auto fill = [&](int s, int j) {
#pragma unroll
        for (int i = 0; i < 16; i++) {
            int ch  = tid + i*256;           // 0..4095 16B chunks
            int rg  = ch >> 10;              // 0:AH 1:AL 2:BH 3:BL
            int off = (ch & 1023) * 4;       // u32 offset within region
            const unsigned* sp;
            if      (rg == 0) sp = aH + (size_t)j*4096 + off;
            else if (rg == 1) sp = aL + (size_t)j*4096 + off;
            else if (rg == 2) sp = bH + (size_t)j*4096 + off;
            else              sp = bL + (size_t)j*4096 + off;
            uint32_t dst = sbase + (s*GSTAGE + rg*4096u + off) * 4u;
            asm volatile("cp.async.cg.shared.global [%0], [%1], 16;" :: "r"(dst), "l"(sp));
        }
        asm volatile("cp.async.commit_group;" ::: "memory");
    };

    fill(0, 0); fill(1, 1); fill(2, 2);      // KT >= 16 at every call site

    for (int j = 0; j < KT; j++) {
        int s = j % 3;
        asm volatile("cp.async.wait_group %0;" :: "n"(2) : "memory");
        __syncthreads();
        const uint4* A_Hs = (const uint4*)(smem + s*GSTAGE);
        const uint4* A_Ls = (const uint4*)(smem + s*GSTAGE + 4096);
        const uint2* B_Hs = (const uint2*)(smem + s*GSTAGE + 8192);
        const uint2* B_Ls = (const uint2*)(smem + s*GSTAGE + 12288);
#pragma unroll
        for (int ks = 0; ks < 4; ks++) {
            uint4 a0H = A_Hs[((wm*2+0)*4 + ks)*32 + lane];
            uint4 a1H = A_Hs[((wm*2+1)*4 + ks)*32 + lane];
            uint4 a0L = A_Ls[((wm*2+0)*4 + ks)*32 + lane];
            uint4 a1L = A_Ls[((wm*2+1)*4 + ks)*32 + lane];
#pragma unroll
            for (int nf = 0; nf < 8; nf++) {
                int bi = ((wn*8 + nf)*4 + ks)*32 + lane;
                uint2 bh = B_Hs[bi];
                uint2 bl = B_Ls[bi];
                mma16(c[0][nf], a0H, bh);
                mma16(c[1][nf], a1H, bh);
                mma16(c[0][nf], a0H, bl);
                mma16(c[1][nf], a1H, bl);
                mma16(c[0][nf], a0L, bh);
                mma16(c[1][nf], a1L, bh);
            }
        }
        __syncthreads();
        if (j + 3 < KT) fill(s, j + 3);
        else asm volatile("cp.async.commit_group;" ::: "memory");
    }

    int g = lane >> 2, t = lane & 3;
#pragma unroll
    for (int mf = 0; mf < 2; mf++) {
#pragma unroll
        for (int nf = 0; nf < 8; nf++) {
            int r  = mt*128 + wm*32 + mf*16 + g;
            int cc = nt*128 + wn*64 + nf*8 + 2*t;
            float* p0 = C + (size_t)r*N + cc;
            float* p1 = C + (size_t)(r+8)*N + cc;
            float2 v0 = make_float2(c[mf][nf][0], c[mf][nf][1]);
            float2 v1 = make_float2(c[mf][nf][2], c[mf][nf][3]);
            if (accum) {
                float2 o0 = *reinterpret_cast<float2*>(p0);
                float2 o1 = *reinterpret_cast<float2*>(p1);
                v0.x += o0.x; v0.y += o0.y; v1.x += o1.x; v1.y += o1.y;
            }
            *reinterpret_cast<float2*>(p0) = v0;
            *reinterpret_cast<float2*>(p1) = v1;
        }
    }
}

// ---------------------------------------------------------------------------
// Non-GEMM kernels (proven)
// ---------------------------------------------------------------------------
__global__ void embed_kernel(const int* __restrict__ ids,
                             const float* __restrict__ emb,
                             float* __restrict__ x, float* __restrict__ dx)
{
    int m = blockIdx.y;
    int d = blockIdx.x * 256 + threadIdx.x;
    int id = ids[m];
    x [(size_t)m*kD + d] = emb[(size_t)id*kD + d];
    dx[(size_t)m*kD + d] = 0.0f;
}

__global__ void rms_jvp_kernel(const float* __restrict__ x,
                               const float* __restrict__ dx,
                               const float* __restrict__ g,
                               float* __restrict__ h, float* __restrict__ dh,
                               int sum_mode)
{
    int m = blockIdx.x;
    const float* xr  = x  + (size_t)m*kD;
    const float* dxr = dx + (size_t)m*kD;
    int t = threadIdx.x;   // 256
    float xv[4], dv[4];
    float s2 = 0.f, sxd = 0.f;
#pragma unroll
    for (int i = 0; i < 4; i++) {
        int d = t + i*256;
        xv[i] = xr[d]; dv[i] = dxr[d];
        s2  += xv[i]*xv[i];
        sxd += xv[i]*dv[i];
    }
    __shared__ float shA[8], shB[8], bc[2];
#pragma unroll
    for (int o = 16; o > 0; o >>= 1) {
        s2  += __shfl_xor_sync(0xffffffffu, s2 , o);
        sxd += __shfl_xor_sync(0xffffffffu, sxd, o);
    }
    int w = t >> 5;
    if ((t & 31) == 0) { shA[w] = s2; shB[w] = sxd; }
    __syncthreads();
    if (t < 32) {
        float a = (t < 8) ? shA[t] : 0.f;
        float b = (t < 8) ? shB[t] : 0.f;
#pragma unroll
        for (int o = 4; o > 0; o >>= 1) {
            a += __shfl_xor_sync(0xffffffffu, a, o);
            b += __shfl_xor_sync(0xffffffffu, b, o);
        }
        if (t == 0) { bc[0] = a; bc[1] = b; }
    }
    __syncthreads();
    float m2 = bc[0] * (1.0f/kD) + RMS_EPS;
    float n  = 1.0f / sqrtf(m2);
    float c  = (bc[1] * (1.0f/kD)) / m2;
#pragma unroll
    for (int i = 0; i < 4; i++) {
        int d = t + i*256;
        float gv = g[d];
        if (sum_mode) {
            h[(size_t)m*kD + d] = gv*n*(xv[i] + dv[i] - xv[i]*c);
        } else {
            h [(size_t)m*kD + d] = gv*n*xv[i];
            dh[(size_t)m*kD + d] = gv*n*(dv[i] - xv[i]*c);
        }
    }
}

__global__ void lora_t_kernel(const float* __restrict__ h,
                              const float* __restrict__ A0,
                              float* __restrict__ T)
{
    int m = blockIdx.x, r = blockIdx.y;
    const float* hr = h  + (size_t)m*kD;
    const float* ar = A0 + (size_t)r*kD;
    float s = 0.f;
    for (int d = threadIdx.x; d < kD; d += 128) s += hr[d]*ar[d];
#pragma unroll
    for (int o = 16; o > 0; o >>= 1) s += __shfl_xor_sync(0xffffffffu, s, o);
    __shared__ float sh[4];
    if ((threadIdx.x & 31) == 0) sh[threadIdx.x >> 5] = s;
    __syncthreads();
    if (threadIdx.x == 0) T[(size_t)m*kR + r] = sh[0]+sh[1]+sh[2]+sh[3];
}

__global__ void lora_add_kernel(const float* __restrict__ T,
                                const float* __restrict__ Bm,
                                float* __restrict__ dq)
{
    int m = blockIdx.y;
    int n = blockIdx.x * 256 + threadIdx.x;
    __shared__ float ts[kR];
    if (threadIdx.x < kR) ts[threadIdx.x] = T[(size_t)m*kR + threadIdx.x];
    __syncthreads();
    float s = 0.f;
#pragma unroll
    for (int r = 0; r < kR; r++) s += ts[r]*Bm[(size_t)n*kR + r];
    dq[(size_t)m*kD + n] += LORA_S * s;
}

__global__ void __launch_bounds__(256)
attn_scores_kernel(const float* __restrict__ q, const float* __restrict__ k,
                   const float* __restrict__ dq, const float* __restrict__ dk,
                   float* __restrict__ sc, float* __restrict__ dsc)
{
    int jt = blockIdx.x, it = blockIdx.y, bh = blockIdx.z;
    if (jt > it) return;
    int b = bh >> 4, hh = bh & 15;
    size_t bse = (size_t)b*kS*kD + (size_t)hh*kHD;
    const float* qb  = q  + bse;
    const float* kb  = k  + bse;
    const float* dqb = dq + bse;
    const float* dkb = dk + bse;
    float* sb  = sc  + (size_t)bh*kS*kS;
    float* dsb = dsc + (size_t)bh*kS*kS;
    int i0 = it*64, j0 = jt*64;

    __shared__ float Qs[16][64], dQs[16][64], Ks[16][64], dKs[16][64];
    int tid = threadIdx.x, tx = tid & 15, ty = tid >> 4;
    float acc[4][4], dacc[4][4];
#pragma unroll
    for (int i = 0; i < 4; i++)
#pragma unroll
        for (int j = 0; j < 4; j++) { acc[i][j] = 0.f; dacc[i][j] = 0.f; }

    for (int kc = 0; kc < kHD; kc += 16) {
#pragma unroll
        for (int i = 0; i < 4; i++) {
            int idx = tid + i*256;
            int rr = idx >> 4, cc = idx & 15;
            Qs [cc][rr] = qb [(size_t)(i0+rr)*kD + kc + cc];
            dQs[cc][rr] = dqb[(size_t)(i0+rr)*kD + kc + cc];
            Ks [cc][rr] = kb [(size_t)(j0+rr)*kD + kc + cc];
            dKs[cc][rr] = dkb[(size_t)(j0+rr)*kD + kc + cc];
        }
        __syncthreads();
#pragma unroll
        for (int d = 0; d < 16; d++) {
            float a[4], da[4], bv[4], dbv[4];
#pragma unroll
            for (int i = 0; i < 4; i++) { a[i] = Qs[d][ty*4+i]; da[i] = dQs[d][ty*4+i]; }
#pragma unroll
            for (int j = 0; j < 4; j++) { bv[j] = Ks[d][tx*4+j]; dbv[j] = dKs[d][tx*4+j]; }
#pragma unroll
            for (int i = 0; i < 4; i++)
#pragma unroll
                for (int j = 0; j < 4; j++) {
                    acc [i][j] += a[i]*bv[j];
                    dacc[i][j] += da[i]*bv[j] + a[i]*dbv[j];
                }
        }
        __syncthreads();
    }
#pragma unroll
    for (int i = 0; i < 4; i++) {
        int row = i0 + ty*4 + i;
#pragma unroll
        for (int j = 0; j < 4; j++) {
            int col = j0 + tx*4 + j;
            sb [(size_t)row*kS + col] = acc [i][j]*0.125f;
            dsb[(size_t)row*kS + col] = dacc[i][j]*0.125f;
        }
    }
}

__global__ void softmax_jvp_kernel(float* __restrict__ sc, float* __restrict__ dsc)
{
    int i = blockIdx.x, bh = blockIdx.y;
    float* sr  = sc  + ((size_t)bh*kS + i)*kS;
    float* dsr = dsc + ((size_t)bh*kS + i)*kS;
    int len = i + 1;
    int t = threadIdx.x;  // 256
    __shared__ float shA[8], shB[8], bc[3];

    float mx = -1e30f;
    for (int j = t; j < len; j += 256) mx = fmaxf(mx, sr[j]);
#pragma unroll
    for (int o = 16; o > 0; o >>= 1) mx = fmaxf(mx, __shfl_xor_sync(0xffffffffu, mx, o));
    if ((t & 31) == 0) shA[t >> 5] = mx;
    __syncthreads();
    if (t < 32) {
        float r = (t < 8) ? shA[t] : -1e30f;
#pragma unroll
        for (int o = 4; o > 0; o >>= 1) r = fmaxf(r, __shfl_xor_sync(0xffffffffu, r, o));
        if (t == 0) bc[0] = r;
    }
    __syncthreads();
    mx = bc[0];
    __syncthreads();

    float Z = 0.f, T2 = 0.f;
    for (int j = t; j < len; j += 256) {
        float e = expf(sr[j] - mx);
        sr[j] = e;
        Z  += e;
        T2 += e * dsr[j];
    }
#pragma unroll
    for (int o = 16; o > 0; o >>= 1) {
        Z  += __shfl_xor_sync(0xffffffffu, Z , o);
        T2 += __shfl_xor_sync(0xffffffffu, T2, o);
    }
    if ((t & 31) == 0) { shA[t >> 5] = Z; shB[t >> 5] = T2; }
    __syncthreads();
    if (t < 32) {
        float a = (t < 8) ? shA[t] : 0.f;
        float b = (t < 8) ? shB[t] : 0.f;
#pragma unroll
        for (int o = 4; o > 0; o >>= 1) {
            a += __shfl_xor_sync(0xffffffffu, a, o);
            b += __shfl_xor_sync(0xffffffffu, b, o);
        }
        if (t == 0) { bc[1] = a; bc[2] = b; }
    }
    __syncthreads();
    float inv = 1.0f / bc[1];
    float sd  = bc[2] * inv;

    for (int j = t; j < len; j += 256) {
        float p = sr[j] * inv;
        sr[j]  = p;
        dsr[j] = p * (dsr[j] - sd);
    }
    int pad = ((i >> 6) + 1) << 6;
    if (pad > kS) pad = kS;
    for (int j = len + t; j < pad; j += 256) { sr[j] = 0.f; dsr[j] = 0.f; }
}

__global__ void __launch_bounds__(256)
attn_o_kernel(const float* __restrict__ p, const float* __restrict__ dp,
              const float* __restrict__ v, const float* __restrict__ dv,
              float* __restrict__ o, float* __restrict__ dout)
{
    int it = blockIdx.x, bh = blockIdx.y;
    int b = bh >> 4, hh = bh & 15;
    const float* pb  = p  + (size_t)bh*kS*kS + (size_t)it*64*kS;
    const float* dpb = dp + (size_t)bh*kS*kS + (size_t)it*64*kS;
    size_t vbase = (size_t)b*kS*kD + (size_t)hh*kHD;
    const float* vb  = v  + vbase;
    const float* dvb = dv + vbase;
    float* ob  = o    + vbase + (size_t)it*64*kD;
    float* dob = dout + vbase + (size_t)it*64*kD;
    int Kend = (it + 1) * 64;

    __shared__ float Ps[16][64], dPs[16][64], Vs[16][64], dVs[16][64];
    int tid = threadIdx.x, tx = tid & 15, ty = tid >> 4;
    float acc[4][4], dacc[4][4];
#pragma unroll
    for (int i = 0; i < 4; i++)
#pragma unroll
        for (int j = 0; j < 4; j++) { acc[i][j] = 0.f; dacc[i][j] = 0.f; }

    for (int k0 = 0; k0 < Kend; k0 += 16) {
#pragma unroll
        for (int i = 0; i < 4; i++) {
            int idx = tid + i*256;
            {
                int rr = idx >> 4, cc = idx & 15;
                Ps [cc][rr] = pb [(size_t)rr*kS + k0 + cc];
                dPs[cc][rr] = dpb[(size_t)rr*kS + k0 + cc];
            }
            {
                int jj = idx >> 6, n = idx & 63;
                Vs [jj][n] = vb [(size_t)(k0+jj)*kD + n];
                dVs[jj][n] = dvb[(size_t)(k0+jj)*kD + n];
            }
        }
        __syncthreads();
#pragma unroll
        for (int d = 0; d < 16; d++) {
            float a[4], da[4], bv[4], dbv[4];
#pragma unroll
            for (int i = 0; i < 4; i++) { a[i] = Ps[d][ty*4+i]; da[i] = dPs[d][ty*4+i]; }
#pragma unroll
            for (int j = 0; j < 4; j++) { bv[j] = Vs[d][tx*4+j]; dbv[j] = dVs[d][tx*4+j]; }
#pragma unroll
            for (int i = 0; i < 4; i++)
#pragma unroll
                for (int j = 0; j < 4; j++) {
                    acc [i][j] += a[i]*bv[j];
                    dacc[i][j] += da[i]*bv[j] + a[i]*dbv[j];
                }
        }
        __syncthreads();
    }
#pragma unroll
    for (int i = 0; i < 4; i++) {
        int row = ty*4 + i;
#pragma unroll
        for (int j = 0; j < 4; j++) {
            int col = tx*4 + j;
            ob [(size_t)row*kD + col] = acc [i][j];
            dob[(size_t)row*kD + col] = dacc[i][j];
        }
    }
}

__global__ void gelu_jvp_kernel(float* __restrict__ u, float* __restrict__ du, int n)
{
    int i = blockIdx.x * 256 + threadIdx.x;
    if (i >= n) return;
    float x = u[i], dx = du[i];
    const float c = 0.7978845608028654f, a = 0.044715f;
    float x2 = x*x;
    float w  = c*(x + a*x*x2);
    float t  = tanhf(w);
    float g  = 0.5f*x*(1.f + t);
    float gp = 0.5f*(1.f + t) + 0.5f*x*(1.f - t*t)*c*(1.f + 3.f*a*x2);
    u[i]  = g;
    du[i] = gp*dx;
}

// ---------------------------------------------------------------------------
// Host orchestration
// ---------------------------------------------------------------------------
static void splitA(const float* src, unsigned* dH, unsigned* dL, int M, int K) {
    splitA16_kernel<<<dim3(K/64, M/128), 256>>>(src, dH, dL, M, K);
}
static void splitB(const float* src, unsigned* dH, unsigned* dL, int K, int N) {
    splitB16_kernel<<<dim3(N/128, K/64), 256>>>(src, dH, dL, K, N);
}
static void hgemm(const unsigned* aH, const unsigned* aL,
                  const unsigned* bH, const unsigned* bL,
                  float* C, int M, int N, int K, int accum) {
    hgemm3_kernel<<<dim3(N/128, M/128), 256, 3*GSTAGE*4>>>(aH, aL, bH, bL, C, M, N, K, accum);
}

extern "C" void kernel_launch(void* const* d_in, const int* in_sizes, int n_in,
                              void* d_out, int out_size)
{
    (void)in_sizes; (void)n_in; (void)out_size;
    const int*   ids  = (const int*)  d_in[0];
    const float* emb  = (const float*)d_in[1];
    const float* Wq   = (const float*)d_in[2];
    const float* Wk   = (const float*)d_in[3];
    const float* Wv   = (const float*)d_in[4];
    const float* Wo   = (const float*)d_in[5];
    const float* W1   = (const float*)d_in[6];
    const float* W2   = (const float*)d_in[7];
    const float* ln1  = (const float*)d_in[8];
    const float* ln2  = (const float*)d_in[9];
    const float* lnf  = (const float*)d_in[10];
    const float* lmh  = (const float*)d_in[11];
    const float* Aq0  = (const float*)d_in[12];
    const float* Av0  = (const float*)d_in[14];
    const float* Bq   = (const float*)d_in[17];
    const float* Bv   = (const float*)d_in[19];
    float* out = (float*)d_out;

    cudaFuncSetAttribute(hgemm3_kernel,
                         cudaFuncAttributeMaxDynamicSharedMemorySize, 3*GSTAGE*4);

    float *x,*dx,*h,*dh,*q,*k,*v,*dq,*dk,*dv,*o,*dd,*u,*du,*sc,*dsc,*tt;
    cudaGetSymbolAddress((void**)&x,  g_x);
    cudaGetSymbolAddress((void**)&dx, g_dx);
    cudaGetSymbolAddress((void**)&h,  g_h);
    cudaGetSymbolAddress((void**)&dh, g_dh);
    cudaGetSymbolAddress((void**)&q,  g_q);
    cudaGetSymbolAddress((void**)&k,  g_k);
    cudaGetSymbolAddress((void**)&v,  g_v);
    cudaGetSymbolAddress((void**)&dq, g_dq);
    cudaGetSymbolAddress((void**)&dk, g_dk);
    cudaGetSymbolAddress((void**)&dv, g_dv);
    cudaGetSymbolAddress((void**)&o,  g_o);
    cudaGetSymbolAddress((void**)&dd, g_do);
    cudaGetSymbolAddress((void**)&u,  g_u);
    cudaGetSymbolAddress((void**)&du, g_du);
    cudaGetSymbolAddress((void**)&sc, g_sc);
    cudaGetSymbolAddress((void**)&dsc,g_dsc);
    cudaGetSymbolAddress((void**)&tt, g_t);

    unsigned *a1H,*a1L,*a2H,*a2L,*wH,*wL;
    cudaGetSymbolAddress((void**)&a1H, g_a1H);
    cudaGetSymbolAddress((void**)&a1L, g_a1L);
    cudaGetSymbolAddress((void**)&a2H, g_a2H);
    cudaGetSymbolAddress((void**)&a2L, g_a2L);
    cudaGetSymbolAddress((void**)&wH,  g_wH);
    cudaGetSymbolAddress((void**)&wL,  g_wL);

    // weight splits (u32 offsets; each u32 = 2 fp16)
    for (int l = 0; l < kL; l++) {
        size_t b0 = (size_t)l * WLAYER2;
        splitB(Wq + (size_t)l*kD*kD,  wH + b0,            wL + b0,            kD, kD);
        splitB(Wk + (size_t)l*kD*kD,  wH + b0 + DD2,      wL + b0 + DD2,      kD, kD);
        splitB(Wv + (size_t)l*kD*kD,  wH + b0 + 2*DD2,    wL + b0 + 2*DD2,    kD, kD);
        splitB(Wo + (size_t)l*kD*kD,  wH + b0 + 3*DD2,    wL + b0 + 3*DD2,    kD, kD);
        splitB(W1 + (size_t)l*kD*kFF, wH + b0 + 4*DD2,    wL + b0 + 4*DD2,    kD, kFF);
        splitB(W2 + (size_t)l*kFF*kD, wH + b0 + 4*DD2+DF2, wL + b0 + 4*DD2+DF2, kFF, kD);
    }
    size_t lmOff = (size_t)kL * WLAYER2;
    splitB(lmh, wH + lmOff, wL + lmOff, kD, kV);

    embed_kernel<<<dim3(kD/256, kM), 256>>>(ids, emb, x, dx);

    for (int l = 0; l < kL; l++) {
        size_t b0 = (size_t)l * WLAYER2;
        const unsigned *wqH = wH + b0,            *wqL = wL + b0;
        const unsigned *wkH = wH + b0 + DD2,      *wkL = wL + b0 + DD2;
        const unsigned *wvH = wH + b0 + 2*DD2,    *wvL = wL + b0 + 2*DD2;
        const unsigned *woH = wH + b0 + 3*DD2,    *woL = wL + b0 + 3*DD2;
        const unsigned *w1H = wH + b0 + 4*DD2,    *w1L = wL + b0 + 4*DD2;
        const unsigned *w2H = wH + b0 + 4*DD2+DF2,*w2L = wL + b0 + 4*DD2+DF2;

        rms_jvp_kernel<<<kM, 256>>>(x, dx, ln1 + (size_t)l*kD, h, dh, 0);
        splitA(h,  a1H, a1L, kM, kD);
        splitA(dh, a2H, a2L, kM, kD);

        hgemm(a1H, a1L, wqH, wqL, q,  kM, kD, kD, 0);
        hgemm(a1H, a1L, wkH, wkL, k,  kM, kD, kD, 0);
        hgemm(a1H, a1L, wvH, wvL, v,  kM, kD, kD, 0);
        hgemm(a2H, a2L, wqH, wqL, dq, kM, kD, kD, 0);
        hgemm(a2H, a2L, wkH, wkL, dk, kM, kD, kD, 0);
        hgemm(a2H, a2L, wvH, wvL, dv, kM, kD, kD, 0);

        lora_t_kernel<<<dim3(kM, kR), 128>>>(h, Aq0 + (size_t)l*kR*kD, tt);
        lora_add_kernel<<<dim3(kD/256, kM), 256>>>(tt, Bq + (size_t)l*kD*kR, dq);
        lora_t_kernel<<<dim3(kM, kR), 128>>>(h, Av0 + (size_t)l*kR*kD, tt);
        lora_add_kernel<<<dim3(kD/256, kM), 256>>>(tt, Bv + (size_t)l*kD*kR, dv);

        attn_scores_kernel<<<dim3(kS/64, kS/64, kBH), 256>>>(q, k, dq, dk, sc, dsc);
        softmax_jvp_kernel<<<dim3(kS, kBH), 256>>>(sc, dsc);
        attn_o_kernel<<<dim3(kS/64, kBH), 256>>>(sc, dsc, v, dv, o, dd);

        splitA(o,  a1H, a1L, kM, kD);
        splitA(dd, a2H, a2L, kM, kD);
        hgemm(a1H, a1L, woH, woL, x,  kM, kD, kD, 1);
        hgemm(a2H, a2L, woH, woL, dx, kM, kD, kD, 1);

        rms_jvp_kernel<<<kM, 256>>>(x, dx, ln2 + (size_t)l*kD, h, dh, 0);
        splitA(h,  a1H, a1L, kM, kD);
        splitA(dh, a2H, a2L, kM, kD);
        hgemm(a1H, a1L, w1H, w1L, u,  kM, kFF, kD, 0);
        hgemm(a2H, a2L, w1H, w1L, du, kM, kFF, kD, 0);
        gelu_jvp_kernel<<<(kM*kFF)/256, 256>>>(u, du, kM*kFF);
        splitA(u,  a1H, a1L, kM, kFF);
        splitA(du, a2H, a2L, kM, kFF);
        hgemm(a1H, a1L, w2H, w2L, x,  kM, kD, kFF, 1);
        hgemm(a2H, a2L, w2H, w2L, dx, kM, kD, kFF, 1);
    }

    rms_jvp_kernel<<<kM, 256>>>(x, dx, lnf, h, h, 1);
    splitA(h, a1H, a1L, kM, kD);
    hgemm(a1H, a1L, wH + lmOff, wL + lmOff, out, kM, kV, kD, 0);
}

// round 15
// speedup vs baseline: 4.0201x; 1.1938x over previous
#include <cuda_runtime.h>
#include <cuda_fp16.h>
#include <math.h>
#include <stdint.h>

// Problem constants
#define kB   2
#define kS   1024
#define kD   1024
#define kH   16
#define kHD  64
#define kFF  4096
#define kV   32000
#define kR   16
#define kL   2
#define kM   2048          /* B*S */
#define kBH  32            /* B*H */
#define LORA_S 2.0f
#define RMS_EPS 1e-6f

// ---------------------------------------------------------------------------
// fp32 scratch
// ---------------------------------------------------------------------------
__device__ float g_x [kM*kD];
__device__ float g_dx[kM*kD];
__device__ float g_h [kM*kD];
__device__ float g_dh[kM*kD];
__device__ float g_q [kM*kD];
__device__ float g_k [kM*kD];
__device__ float g_v [kM*kD];
__device__ float g_dq[kM*kD];
__device__ float g_dk[kM*kD];
__device__ float g_dv[kM*kD];
__device__ float g_o [kM*kD];
__device__ float g_do[kM*kD];
__device__ float g_u [kM*kFF];
__device__ float g_du[kM*kFF];
__device__ float g_sc [kBH*kS*kS];
__device__ float g_dsc[kBH*kS*kS];
__device__ float g_t [kM*kR];

// fp16 hi/lo planes (2 fp16 per u32), fragment-permuted for m16n8k16
__device__ unsigned g_a1H[(size_t)kM*kFF/2];
__device__ unsigned g_a1L[(size_t)kM*kFF/2];
__device__ unsigned g_a2H[(size_t)kM*kFF/2];
__device__ unsigned g_a2L[(size_t)kM*kFF/2];

// weights (u32 counts; each u32 = 2 fp16)
#define DD2 ((size_t)kD*kD/2)
#define DF2 ((size_t)kD*kFF/2)
#define WLAYER2 (4*DD2 + 2*DF2)
#define LM2 ((size_t)kD*kV/2)
#define WTOT2 (kL*WLAYER2 + LM2)
__device__ unsigned g_wH[WTOT2];
__device__ unsigned g_wL[WTOT2];

// ---------------------------------------------------------------------------
// helpers
// ---------------------------------------------------------------------------
__device__ __forceinline__ uint32_t smem_addr_u32(const void* p) {
    uint32_t a;
    asm("{ .reg .u64 t; cvta.to.shared.u64 t, %1; cvt.u32.u64 %0, t; }"
        : "=r"(a) : "l"(p));
    return a;
}
__device__ __forceinline__ void split_pack(float x, float y, unsigned& H, unsigned& L) {
    __half hx = __float2half_rn(x), hy = __float2half_rn(y);
    float rx = x - __half2float(hx), ry = y - __half2float(hy);
    __half lx = __float2half_rn(rx), ly = __float2half_rn(ry);
    __half2 Hh = __halves2half2(hx, hy);
    __half2 Ll = __halves2half2(lx, ly);
    H = *reinterpret_cast<unsigned*>(&Hh);
    L = *reinterpret_cast<unsigned*>(&Ll);
}
__device__ __forceinline__ void mma16(float* c, uint4 a, uint2 b) {
    asm volatile(
        "mma.sync.aligned.m16n8k16.row.col.f32.f16.f16.f32 "
        "{%0,%1,%2,%3}, {%4,%5,%6,%7}, {%8,%9}, {%0,%1,%2,%3};"
        : "+f"(c[0]), "+f"(c[1]), "+f"(c[2]), "+f"(c[3])
        : "r"(a.x), "r"(a.y), "r"(a.z), "r"(a.w), "r"(b.x), "r"(b.y));
}

// ---------------------------------------------------------------------------
// Split pre-pass, A operand (proven round 9)
// ---------------------------------------------------------------------------
__global__ void __launch_bounds__(256)
splitA16_kernel(const float* __restrict__ src, unsigned* __restrict__ dH,
                unsigned* __restrict__ dL, int M, int K)
{
    __shared__ float ts[128*64];
    int mt = blockIdx.y, kt = blockIdx.x, tid = threadIdx.x;
    int KT = K >> 6;
    const float* sb = src + (size_t)mt*128*K + kt*64;
#pragma unroll
    for (int i = 0; i < 8; i++) {
        int q = tid + i*256;
        int r = q >> 4, c = (q & 15) << 2;
        float4 v = *reinterpret_cast<const float4*>(sb + (size_t)r*K + c);
        ts[r*64+c] = v.x; ts[r*64+c+1] = v.y; ts[r*64+c+2] = v.z; ts[r*64+c+3] = v.w;
    }
    __syncthreads();
    size_t tb = ((size_t)mt*KT + kt) * 4096;
#pragma unroll
    for (int i = 0; i < 4; i++) {
        int q = tid + i*256;
        int lane = q & 31, kstep = (q >> 5) & 3, mfrag = q >> 7;
        int g = lane >> 2, t = lane & 3;
        int r0 = mfrag*16 + g, c0 = kstep*16 + 2*t;
        unsigned h0,h1,h2,h3,l0,l1,l2,l3;
        split_pack(ts[r0*64+c0],       ts[r0*64+c0+1],       h0, l0);
        split_pack(ts[(r0+8)*64+c0],   ts[(r0+8)*64+c0+1],   h1, l1);
        split_pack(ts[r0*64+c0+8],     ts[r0*64+c0+9],       h2, l2);
        split_pack(ts[(r0+8)*64+c0+8], ts[(r0+8)*64+c0+9],   h3, l3);
        *reinterpret_cast<uint4*>(dH + tb + (size_t)q*4) = make_uint4(h0,h1,h2,h3);
        *reinterpret_cast<uint4*>(dL + tb + (size_t)q*4) = make_uint4(l0,l1,l2,l3);
    }
}

// Fused gelu-JVP + A split
__global__ void __launch_bounds__(256)
gelu_split_kernel(const float* __restrict__ u, const float* __restrict__ du,
                  unsigned* __restrict__ d1H, unsigned* __restrict__ d1L,
                  unsigned* __restrict__ d2H, unsigned* __restrict__ d2L,
                  int M, int K)
{
    __shared__ float t1[128*64], t2[128*64];
    int mt = blockIdx.y, kt = blockIdx.x, tid = threadIdx.x;
    int KT = K >> 6;
    const float* ub  = u  + (size_t)mt*128*K + kt*64;
    const float* dub = du + (size_t)mt*128*K + kt*64;
    const float cg = 0.7978845608028654f, ag = 0.044715f;
#pragma unroll
    for (int i = 0; i < 8; i++) {
        int q = tid + i*256;
        int r = q >> 4, c = (q & 15) << 2;
        float4 a = *reinterpret_cast<const float4*>(ub  + (size_t)r*K + c);
        float4 b = *reinterpret_cast<const float4*>(dub + (size_t)r*K + c);
        float xs[4] = {a.x, a.y, a.z, a.w};
        float ds[4] = {b.x, b.y, b.z, b.w};
#pragma unroll
        for (int j = 0; j < 4; j++) {
            float x = xs[j], dxv = ds[j];
            float x2 = x*x;
            float w  = cg*(x + ag*x*x2);
            float t  = tanhf(w);
            float gval = 0.5f*x*(1.f + t);
            float gp = 0.5f*(1.f + t) + 0.5f*x*(1.f - t*t)*cg*(1.f + 3.f*ag*x2);
            t1[r*64+c+j] = gval;
            t2[r*64+c+j] = gp*dxv;
        }
    }
    __syncthreads();
    size_t tb = ((size_t)mt*KT + kt) * 4096;
#pragma unroll
    for (int i = 0; i < 4; i++) {
        int q = tid + i*256;
        int lane = q & 31, kstep = (q >> 5) & 3, mfrag = q >> 7;
        int g = lane >> 2, t = lane & 3;
        int r0 = mfrag*16 + g, c0 = kstep*16 + 2*t;
        unsigned h0,h1,h2,h3,l0,l1,l2,l3;
        split_pack(t1[r0*64+c0],       t1[r0*64+c0+1],       h0, l0);
        split_pack(t1[(r0+8)*64+c0],   t1[(r0+8)*64+c0+1],   h1, l1);
        split_pack(t1[r0*64+c0+8],     t1[r0*64+c0+9],       h2, l2);
        split_pack(t1[(r0+8)*64+c0+8], t1[(r0+8)*64+c0+9],   h3, l3);
        *reinterpret_cast<uint4*>(d1H + tb + (size_t)q*4) = make_uint4(h0,h1,h2,h3);
        *reinterpret_cast<uint4*>(d1L + tb + (size_t)q*4) = make_uint4(l0,l1,l2,l3);
        split_pack(t2[r0*64+c0],       t2[r0*64+c0+1],       h0, l0);
        split_pack(t2[(r0+8)*64+c0],   t2[(r0+8)*64+c0+1],   h1, l1);
        split_pack(t2[r0*64+c0+8],     t2[r0*64+c0+9],       h2, l2);
        split_pack(t2[(r0+8)*64+c0+8], t2[(r0+8)*64+c0+9],   h3, l3);
        *reinterpret_cast<uint4*>(d2H + tb + (size_t)q*4) = make_uint4(h0,h1,h2,h3);
        *reinterpret_cast<uint4*>(d2L + tb + (size_t)q*4) = make_uint4(l0,l1,l2,l3);
    }
}

// ---------------------------------------------------------------------------
// Split pre-pass, B operand (proven round 9)
// ---------------------------------------------------------------------------
__global__ void __launch_bounds__(256)
splitB16_kernel(const float* __restrict__ src, unsigned* __restrict__ dH,
                unsigned* __restrict__ dL, int K, int N)
{
    __shared__ float ts[64*128];
    int nt = blockIdx.x, kt = blockIdx.y, tid = threadIdx.x;
    int KT = K >> 6;
    const float* sb = src + (size_t)kt*64*N + (size_t)nt*128;
#pragma unroll
    for (int i = 0; i < 8; i++) {
        int q = tid + i*256;
        int r = q >> 5, c = (q & 31) << 2;
        float4 v = *reinterpret_cast<const float4*>(sb + (size_t)r*N + c);
        ts[r*128+c] = v.x; ts[r*128+c+1] = v.y; ts[r*128+c+2] = v.z; ts[r*128+c+3] = v.w;
    }
    __syncthreads();
    size_t tb = ((size_t)nt*KT + kt) * 4096;
#pragma unroll
    for (int i = 0; i < 8; i++) {
        int q = tid + i*256;
        int lane = q & 31, kstep = (q >> 5) & 3, nfrag = q >> 7;
        int g = lane >> 2, t = lane & 3;
        int n = nfrag*8 + g, k0 = kstep*16;
        unsigned h0,h1,l0,l1;
        split_pack(ts[(k0+2*t)*128+n],   ts[(k0+2*t+1)*128+n], h0, l0);
        split_pack(ts[(k0+2*t+8)*128+n], ts[(k0+2*t+9)*128+n], h1, l1);
        *reinterpret_cast<uint2*>(dH + tb + (size_t)q*2) = make_uint2(h0,h1);
        *reinterpret_cast<uint2*>(dL + tb + (size_t)q*2) = make_uint2(l0,l1);
    }
}

// ---------------------------------------------------------------------------
// 3xFP16 GEMM (proven round 9)
// ---------------------------------------------------------------------------
#define GSTAGE 16384u

__global__ void __launch_bounds__(256, 1)
hgemm3_kernel(const unsigned* __restrict__ AH, const unsigned* __restrict__ AL,
              const unsigned* __restrict__ BH, const unsigned* __restrict__ BL,
              float* __restrict__ C, int M, int N, int K, int accum)
{
    extern __shared__ unsigned smem[];
    int tid = threadIdx.x, lane = tid & 31, warp = tid >> 5;
    int wm = warp & 3, wn = warp >> 2;
    int nt = blockIdx.x, mt = blockIdx.y;
    int KT = K >> 6;
    const unsigned* aH = AH + (size_t)mt*KT*4096;
    const unsigned* aL = AL + (size_t)mt*KT*4096;
    const unsigned* bH = BH + (size_t)nt*KT*4096;
    const unsigned* bL = BL + (size_t)nt*KT*4096;
    uint32_t sbase = smem_addr_u32(smem);

    float c[2][8][4];
#pragma unroll
    for (int mf = 0; mf < 2; mf++)
#pragma unroll
        for (int nf = 0; nf < 8; nf++)
#pragma unroll
            for (int i = 0; i < 4; i++) c[mf][nf][i] = 0.f;

    auto fill = [&](int s, int j) {
#pragma unroll
        for (int i = 0; i < 16; i++) {
            int ch  = tid + i*256;
            int rg  = ch >> 10;
            int off = (ch & 1023) * 4;
            const unsigned* sp;
            if      (rg == 0) sp = aH + (size_t)j*4096 + off;
            else if (rg == 1) sp = aL + (size_t)j*4096 + off;
            else if (rg == 2) sp = bH + (size_t)j*4096 + off;
            else              sp = bL + (size_t)j*4096 + off;
            uint32_t dst = sbase + (s*GSTAGE + rg*4096u + off) * 4u;
            asm volatile("cp.async.cg.shared.global [%0], [%1], 16;" :: "r"(dst), "l"(sp));
        }
        asm volatile("cp.async.commit_group;" ::: "memory");
    };

    fill(0, 0); fill(1, 1); fill(2, 2);

    for (int j = 0; j < KT; j++) {
        int s = j % 3;
        asm volatile("cp.async.wait_group %0;" :: "n"(2) : "memory");
        __syncthreads();
        const uint4* A_Hs = (const uint4*)(smem + s*GSTAGE);
        const uint4* A_Ls = (const uint4*)(smem + s*GSTAGE + 4096);
        const uint2* B_Hs = (const uint2*)(smem + s*GSTAGE + 8192);
        const uint2* B_Ls = (const uint2*)(smem + s*GSTAGE + 12288);
#pragma unroll
        for (int ks = 0; ks < 4; ks++) {
            uint4 a0H = A_Hs[((wm*2+0)*4 + ks)*32 + lane];
            uint4 a1H = A_Hs[((wm*2+1)*4 + ks)*32 + lane];
            uint4 a0L = A_Ls[((wm*2+0)*4 + ks)*32 + lane];
            uint4 a1L = A_Ls[((wm*2+1)*4 + ks)*32 + lane];
#pragma unroll
            for (int nf = 0; nf < 8; nf++) {
                int bi = ((wn*8 + nf)*4 + ks)*32 + lane;
                uint2 bh = B_Hs[bi];
                uint2 bl = B_Ls[bi];
                mma16(c[0][nf], a0H, bh);
                mma16(c[1][nf], a1H, bh);
                mma16(c[0][nf], a0H, bl);
                mma16(c[1][nf], a1H, bl);
                mma16(c[0][nf], a0L, bh);
                mma16(c[1][nf], a1L, bh);
            }
        }
        __syncthreads();
        if (j + 3 < KT) fill(s, j + 3);
        else asm volatile("cp.async.commit_group;" ::: "memory");
    }

    int g = lane >> 2, t = lane & 3;
#pragma unroll
    for (int mf = 0; mf < 2; mf++) {
#pragma unroll
        for (int nf = 0; nf < 8; nf++) {
            int r  = mt*128 + wm*32 + mf*16 + g;
            int cc = nt*128 + wn*64 + nf*8 + 2*t;
            float* p0 = C + (size_t)r*N + cc;
            float* p1 = C + (size_t)(r+8)*N + cc;
            float2 v0 = make_float2(c[mf][nf][0], c[mf][nf][1]);
            float2 v1 = make_float2(c[mf][nf][2], c[mf][nf][3]);
            if (accum) {
                float2 o0 = *reinterpret_cast<float2*>(p0);
                float2 o1 = *reinterpret_cast<float2*>(p1);
                v0.x += o0.x; v0.y += o0.y; v1.x += o1.x; v1.y += o1.y;
            }
            *reinterpret_cast<float2*>(p0) = v0;
            *reinterpret_cast<float2*>(p1) = v1;
        }
    }
}

// ---------------------------------------------------------------------------
// fp16 mma attention: scores JVP. Tile 64x64, K=HD=64 single shot.
// ---------------------------------------------------------------------------
#define SPAD 65
#define ATTN_SMEM (4*64*SPAD*4)

__global__ void __launch_bounds__(256)
attn_scores_mma(const float* __restrict__ q, const float* __restrict__ k,
                const float* __restrict__ dq, const float* __restrict__ dk,
                float* __restrict__ sc, float* __restrict__ dsc)
{
    int jt = blockIdx.x, it = blockIdx.y, bh = blockIdx.z;
    if (jt > it) return;
    extern __shared__ float sm[];
    float* Qs  = sm;
    float* dQs = sm + 64*SPAD;
    float* Ks  = sm + 2*64*SPAD;
    float* dKs = sm + 3*64*SPAD;

    int b = bh >> 4, hh = bh & 15;
    size_t base = (size_t)b*kS*kD + (size_t)hh*kHD;
    int i0 = it*64, j0 = jt*64;
    int tid = threadIdx.x, lane = tid & 31, warp = tid >> 5;
    int wm = warp & 3, wn = warp >> 2;
    int g = lane >> 2, t = lane & 3;

    const float* srcs[4] = { q  + base + (size_t)i0*kD, dq + base + (size_t)i0*kD,
                             k  + base + (size_t)j0*kD, dk + base + (size_t)j0*kD };
    float* dsts[4] = { Qs, dQs, Ks, dKs };
#pragma unroll
    for (int tl = 0; tl < 4; tl++) {
#pragma unroll
        for (int i = 0; i < 4; i++) {
            int idx = tid + i*256;
            int r = idx >> 4, c = (idx & 15) << 2;
            float4 v = *reinterpret_cast<const float4*>(srcs[tl] + (size_t)r*kD + c);
            float* d = dsts[tl] + r*SPAD + c;
            d[0] = v.x; d[1] = v.y; d[2] = v.z; d[3] = v.w;
        }
    }
    __syncthreads();

    float cs[4][4], cds[4][4];
#pragma unroll
    for (int nf = 0; nf < 4; nf++)
#pragma unroll
        for (int i = 0; i < 4; i++) { cs[nf][i] = 0.f; cds[nf][i] = 0.f; }

#pragma unroll
    for (int ks = 0; ks < 4; ks++) {
        int c0 = ks*16 + 2*t;
        int r0 = wm*16 + g;
        uint4 qH, qL, dqH, dqL;
        split_pack(Qs[r0*SPAD+c0],       Qs[r0*SPAD+c0+1],       qH.x, qL.x);
        split_pack(Qs[(r0+8)*SPAD+c0],   Qs[(r0+8)*SPAD+c0+1],   qH.y, qL.y);
        split_pack(Qs[r0*SPAD+c0+8],     Qs[r0*SPAD+c0+9],       qH.z, qL.z);
        split_pack(Qs[(r0+8)*SPAD+c0+8], Qs[(r0+8)*SPAD+c0+9],   qH.w, qL.w);
        split_pack(dQs[r0*SPAD+c0],       dQs[r0*SPAD+c0+1],     dqH.x, dqL.x);
        split_pack(dQs[(r0+8)*SPAD+c0],   dQs[(r0+8)*SPAD+c0+1], dqH.y, dqL.y);
        split_pack(dQs[r0*SPAD+c0+8],     dQs[r0*SPAD+c0+9],     dqH.z, dqL.z);
        split_pack(dQs[(r0+8)*SPAD+c0+8], dQs[(r0+8)*SPAD+c0+9], dqH.w, dqL.w);
#pragma unroll
        for (int nf = 0; nf < 4; nf++) {
            int n = wn*32 + nf*8 + g;
            uint2 keH, keL, dkeH, dkeL;
            split_pack(Ks[n*SPAD+c0],   Ks[n*SPAD+c0+1], keH.x, keL.x);
            split_pack(Ks[n*SPAD+c0+8], Ks[n*SPAD+c0+9], keH.y, keL.y);
            split_pack(dKs[n*SPAD+c0],   dKs[n*SPAD+c0+1], dkeH.x, dkeL.x);
            split_pack(dKs[n*SPAD+c0+8], dKs[n*SPAD+c0+9], dkeH.y, dkeL.y);
            mma16(cs[nf],  qH,  keH);  mma16(cs[nf],  qH,  keL);  mma16(cs[nf],  qL,  keH);
            mma16(cds[nf], dqH, keH);  mma16(cds[nf], dqH, keL);  mma16(cds[nf], dqL, keH);
            mma16(cds[nf], qH,  dkeH); mma16(cds[nf], qH,  dkeL); mma16(cds[nf], qL,  dkeH);
        }
    }

    float* sb  = sc  + (size_t)bh*kS*kS;
    float* dsb = dsc + (size_t)bh*kS*kS;
#pragma unroll
    for (int nf = 0; nf < 4; nf++) {
#pragma unroll
        for (int idx = 0; idx < 4; idx++) {
            int row = i0 + wm*16 + g + ((idx >= 2) ? 8 : 0);
            int col = j0 + wn*32 + nf*8 + 2*t + (idx & 1);
            sb [(size_t)row*kS + col] = cs [nf][idx] * 0.125f;
            dsb[(size_t)row*kS + col] = cds[nf][idx] * 0.125f;
        }
    }
}

// ---------------------------------------------------------------------------
// fp16 mma AV JVP
// ---------------------------------------------------------------------------
__global__ void __launch_bounds__(256)
attn_o_mma(const float* __restrict__ p, const float* __restrict__ dp,
           const float* __restrict__ v, const float* __restrict__ dv,
           float* __restrict__ o, float* __restrict__ dout)
{
    int it = blockIdx.x, bh = blockIdx.y;
    int b = bh >> 4, hh = bh & 15;
    extern __shared__ float sm[];
    float* Ps  = sm;
    float* dPs = sm + 64*SPAD;
    float* Vs  = sm + 2*64*SPAD;
    float* dVs = sm + 3*64*SPAD;

    const float* pb  = p  + (size_t)bh*kS*kS + (size_t)it*64*kS;
    const float* dpb = dp + (size_t)bh*kS*kS + (size_t)it*64*kS;
    size_t vbase = (size_t)b*kS*kD + (size_t)hh*kHD;
    const float* vb  = v  + vbase;
    const float* dvb = dv + vbase;
    float* ob  = o    + vbase + (size_t)it*64*kD;
    float* dob = dout + vbase + (size_t)it*64*kD;

    int tid = threadIdx.x, lane = tid & 31, warp = tid >> 5;
    int wm = warp & 3, wn = warp >> 2;
    int g = lane >> 2, t = lane & 3;

    float cs[4][4], cds[4][4];
#pragma unroll
    for (int nf = 0; nf < 4; nf++)
#pragma unroll
        for (int i = 0; i < 4; i++) { cs[nf][i] = 0.f; cds[nf][i] = 0.f; }

    for (int kb = 0; kb <= it; kb++) {
#pragma unroll
        for (int i = 0; i < 4; i++) {
            int idx = tid + i*256;
            int r = idx >> 4, c = (idx & 15) << 2;
            float4 a = *reinterpret_cast<const float4*>(pb  + (size_t)r*kS + kb*64 + c);
            float4 bq = *reinterpret_cast<const float4*>(dpb + (size_t)r*kS + kb*64 + c);
            float* d0 = Ps  + r*SPAD + c;
            float* d1 = dPs + r*SPAD + c;
            d0[0]=a.x; d0[1]=a.y; d0[2]=a.z; d0[3]=a.w;
            d1[0]=bq.x; d1[1]=bq.y; d1[2]=bq.z; d1[3]=bq.w;
            float4 vv = *reinterpret_cast<const float4*>(vb  + (size_t)(kb*64+r)*kD + c);
            float4 dvv= *reinterpret_cast<const float4*>(dvb + (size_t)(kb*64+r)*kD + c);
            float* d2 = Vs  + r*SPAD + c;
            float* d3 = dVs + r*SPAD + c;
            d2[0]=vv.x; d2[1]=vv.y; d2[2]=vv.z; d2[3]=vv.w;
            d3[0]=dvv.x; d3[1]=dvv.y; d3[2]=dvv.z; d3[3]=dvv.w;
        }
        __syncthreads();

#pragma unroll
        for (int ks = 0; ks < 4; ks++) {
            int c0 = ks*16 + 2*t;
            int r0 = wm*16 + g;
            uint4 pH, pL, dpH, dpL;
            split_pack(Ps[r0*SPAD+c0],       Ps[r0*SPAD+c0+1],       pH.x, pL.x);
            split_pack(Ps[(r0+8)*SPAD+c0],   Ps[(r0+8)*SPAD+c0+1],   pH.y, pL.y);
            split_pack(Ps[r0*SPAD+c0+8],     Ps[r0*SPAD+c0+9],       pH.z, pL.z);
            split_pack(Ps[(r0+8)*SPAD+c0+8], Ps[(r0+8)*SPAD+c0+9],   pH.w, pL.w);
            split_pack(dPs[r0*SPAD+c0],       dPs[r0*SPAD+c0+1],     dpH.x, dpL.x);
            split_pack(dPs[(r0+8)*SPAD+c0],   dPs[(r0+8)*SPAD+c0+1], dpH.y, dpL.y);
            split_pack(dPs[r0*SPAD+c0+8],     dPs[r0*SPAD+c0+9],     dpH.z, dpL.z);
            split_pack(dPs[(r0+8)*SPAD+c0+8], dPs[(r0+8)*SPAD+c0+9], dpH.w, dpL.w);
#pragma unroll
            for (int nf = 0; nf < 4; nf++) {
                int n = wn*32 + nf*8 + g;
                uint2 vH, vL, dvH, dvL;
                split_pack(Vs[(c0)*SPAD+n],   Vs[(c0+1)*SPAD+n], vH.x, vL.x);
                split_pack(Vs[(c0+8)*SPAD+n], Vs[(c0+9)*SPAD+n], vH.y, vL.y);
                split_pack(dVs[(c0)*SPAD+n],   dVs[(c0+1)*SPAD+n], dvH.x, dvL.x);
                split_pack(dVs[(c0+8)*SPAD+n], dVs[(c0+9)*SPAD+n], dvH.y, dvL.y);
                mma16(cs[nf],  pH,  vH);  mma16(cs[nf],  pH,  vL);  mma16(cs[nf],  pL,  vH);
                mma16(cds[nf], dpH, vH);  mma16(cds[nf], dpH, vL);  mma16(cds[nf], dpL, vH);
                mma16(cds[nf], pH,  dvH); mma16(cds[nf], pH,  dvL); mma16(cds[nf], pL,  dvH);
            }
        }
        __syncthreads();
    }

#pragma unroll
    for (int nf = 0; nf < 4; nf++) {
#pragma unroll
        for (int idx = 0; idx < 4; idx++) {
            int row = wm*16 + g + ((idx >= 2) ? 8 : 0);
            int col = wn*32 + nf*8 + 2*t + (idx & 1);
            ob [(size_t)row*kD + col] = cs [nf][idx];
            dob[(size_t)row*kD + col] = cds[nf][idx];
        }
    }
}

// ---------------------------------------------------------------------------
// Non-GEMM kernels
// ---------------------------------------------------------------------------
__global__ void embed_kernel(const int* __restrict__ ids,
                             const float* __restrict__ emb,
                             float* __restrict__ x, float* __restrict__ dx)
{
    int m = blockIdx.y;
    int d = blockIdx.x * 256 + threadIdx.x;
    int id = ids[m];
    x [(size_t)m*kD + d] = emb[(size_t)id*kD + d];
    dx[(size_t)m*kD + d] = 0.0f;
}

__global__ void zero_kernel(float* __restrict__ p, int n4)
{
    int i = blockIdx.x * 256 + threadIdx.x;
    if (i < n4) reinterpret_cast<float4*>(p)[i] = make_float4(0.f,0.f,0.f,0.f);
}

__global__ void rms_jvp_kernel(const float* __restrict__ x,
                               const float* __restrict__ dx,
                               const float* __restrict__ g,
                               float* __restrict__ h, float* __restrict__ dh,
                               int sum_mode)
{
    int m = blockIdx.x;
    const float* xr  = x  + (size_t)m*kD;
    const float* dxr = dx + (size_t)m*kD;
    int t = threadIdx.x;
    float xv[4], dv[4];
    float s2 = 0.f, sxd = 0.f;
#pragma unroll
    for (int i = 0; i < 4; i++) {
        int d = t + i*256;
        xv[i] = xr[d]; dv[i] = dxr[d];
        s2  += xv[i]*xv[i];
        sxd += xv[i]*dv[i];
    }
    __shared__ float shA[8], shB[8], bc[2];
#pragma unroll
    for (int o = 16; o > 0; o >>= 1) {
        s2  += __shfl_xor_sync(0xffffffffu, s2 , o);
        sxd += __shfl_xor_sync(0xffffffffu, sxd, o);
    }
    int w = t >> 5;
    if ((t & 31) == 0) { shA[w] = s2; shB[w] = sxd; }
    __syncthreads();
    if (t < 32) {
        float a = (t < 8) ? shA[t] : 0.f;
        float b = (t < 8) ? shB[t] : 0.f;
#pragma unroll
        for (int o = 4; o > 0; o >>= 1) {
            a += __shfl_xor_sync(0xffffffffu, a, o);
            b += __shfl_xor_sync(0xffffffffu, b, o);
        }
        if (t == 0) { bc[0] = a; bc[1] = b; }
    }
    __syncthreads();
    float m2 = bc[0] * (1.0f/kD) + RMS_EPS;
    float n  = 1.0f / sqrtf(m2);
    float c  = (bc[1] * (1.0f/kD)) / m2;
#pragma unroll
    for (int i = 0; i < 4; i++) {
        int d = t + i*256;
        float gv = g[d];
        if (sum_mode) {
            h[(size_t)m*kD + d] = gv*n*(xv[i] + dv[i] - xv[i]*c);
        } else {
            h [(size_t)m*kD + d] = gv*n*xv[i];
            dh[(size_t)m*kD + d] = gv*n*(dv[i] - xv[i]*c);
        }
    }
}

__global__ void lora_t_kernel(const float* __restrict__ h,
                              const float* __restrict__ A0,
                              float* __restrict__ T)
{
    int m = blockIdx.x, r = blockIdx.y;
    const float* hr = h  + (size_t)m*kD;
    const float* ar = A0 + (size_t)r*kD;
    float s = 0.f;
    for (int d = threadIdx.x; d < kD; d += 128) s += hr[d]*ar[d];
#pragma unroll
    for (int o = 16; o > 0; o >>= 1) s += __shfl_xor_sync(0xffffffffu, s, o);
    __shared__ float sh[4];
    if ((threadIdx.x & 31) == 0) sh[threadIdx.x >> 5] = s;
    __syncthreads();
    if (threadIdx.x == 0) T[(size_t)m*kR + r] = sh[0]+sh[1]+sh[2]+sh[3];
}

__global__ void lora_add_kernel(const float* __restrict__ T,
                                const float* __restrict__ Bm,
                                float* __restrict__ dq, int wr)
{
    int m = blockIdx.y;
    int n = blockIdx.x * 256 + threadIdx.x;
    __shared__ float ts[kR];
    if (threadIdx.x < kR) ts[threadIdx.x] = T[(size_t)m*kR + threadIdx.x];
    __syncthreads();
    float s = 0.f;
#pragma unroll
    for (int r = 0; r < kR; r++) s += ts[r]*Bm[(size_t)n*kR + r];
    if (wr) dq[(size_t)m*kD + n] = LORA_S * s;
    else    dq[(size_t)m*kD + n] += LORA_S * s;
}

__global__ void softmax_jvp_kernel(float* __restrict__ sc, float* __restrict__ dsc)
{
    int i = blockIdx.x, bh = blockIdx.y;
    float* sr  = sc  + ((size_t)bh*kS + i)*kS;
    float* dsr = dsc + ((size_t)bh*kS + i)*kS;
    int len = i + 1;
    int t = threadIdx.x;
    __shared__ float shA[8], shB[8], bc[3];

    float mx = -1e30f;
    for (int j = t; j < len; j += 256) mx = fmaxf(mx, sr[j]);
#pragma unroll
    for (int o = 16; o > 0; o >>= 1) mx = fmaxf(mx, __shfl_xor_sync(0xffffffffu, mx, o));
    if ((t & 31) == 0) shA[t >> 5] = mx;
    __syncthreads();
    if (t < 32) {
        float r = (t < 8) ? shA[t] : -1e30f;
#pragma unroll
        for (int o = 4; o > 0; o >>= 1) r = fmaxf(r, __shfl_xor_sync(0xffffffffu, r, o));
        if (t == 0) bc[0] = r;
    }
    __syncthreads();
    mx = bc[0];
    __syncthreads();

    float Z = 0.f, T2 = 0.f;
    for (int j = t; j < len; j += 256) {
        float e = expf(sr[j] - mx);
        sr[j] = e;
        Z  += e;
        T2 += e * dsr[j];
    }
#pragma unroll
    for (int o = 16; o > 0; o >>= 1) {
        Z  += __shfl_xor_sync(0xffffffffu, Z , o);
        T2 += __shfl_xor_sync(0xffffffffu, T2, o);
    }
    if ((t & 31) == 0) { shA[t >> 5] = Z; shB[t >> 5] = T2; }
    __syncthreads();
    if (t < 32) {
        float a = (t < 8) ? shA[t] : 0.f;
        float b = (t < 8) ? shB[t] : 0.f;
#pragma unroll
        for (int o = 4; o > 0; o >>= 1) {
            a += __shfl_xor_sync(0xffffffffu, a, o);
            b += __shfl_xor_sync(0xffffffffu, b, o);
        }
        if (t == 0) { bc[1] = a; bc[2] = b; }
    }
    __syncthreads();
    float inv = 1.0f / bc[1];
    float sd  = bc[2] * inv;

    for (int j = t; j < len; j += 256) {
        float pp = sr[j] * inv;
        sr[j]  = pp;
        dsr[j] = pp * (dsr[j] - sd);
    }
    int pad = ((i >> 6) + 1) << 6;
    if (pad > kS) pad = kS;
    for (int j = len + t; j < pad; j += 256) { sr[j] = 0.f; dsr[j] = 0.f; }
}

// ---------------------------------------------------------------------------
// Host orchestration
// ---------------------------------------------------------------------------
static void splitA(const float* src, unsigned* dH, unsigned* dL, int M, int K) {
    splitA16_kernel<<<dim3(K/64, M/128), 256>>>(src, dH, dL, M, K);
}
static void splitB(const float* src, unsigned* dH, unsigned* dL, int K, int N) {
    splitB16_kernel<<<dim3(N/128, K/64), 256>>>(src, dH, dL, K, N);
}
static void hgemm(const unsigned* aH, const unsigned* aL,
                  const unsigned* bH, const unsigned* bL,
                  float* C, int M, int N, int K, int accum) {
    hgemm3_kernel<<<dim3(N/128, M/128), 256, 3*GSTAGE*4>>>(aH, aL, bH, bL, C, M, N, K, accum);
}

extern "C" void kernel_launch(void* const* d_in, const int* in_sizes, int n_in,
                              void* d_out, int out_size)
{
    (void)in_sizes; (void)n_in; (void)out_size;
    const int*   ids  = (const int*)  d_in[0];
    const float* emb  = (const float*)d_in[1];
    const float* Wq   = (const float*)d_in[2];
    const float* Wk   = (const float*)d_in[3];
    const float* Wv   = (const float*)d_in[4];
    const float* Wo   = (const float*)d_in[5];
    const float* W1   = (const float*)d_in[6];
    const float* W2   = (const float*)d_in[7];
    const float* ln1  = (const float*)d_in[8];
    const float* ln2  = (const float*)d_in[9];
    const float* lnf  = (const float*)d_in[10];
    const float* lmh  = (const float*)d_in[11];
    const float* Aq0  = (const float*)d_in[12];
    const float* Av0  = (const float*)d_in[14];
    const float* Bq   = (const float*)d_in[17];
    const float* Bv   = (const float*)d_in[19];
    float* out = (float*)d_out;

    cudaFuncSetAttribute(hgemm3_kernel,
                         cudaFuncAttributeMaxDynamicSharedMemorySize, 3*GSTAGE*4);
    cudaFuncSetAttribute(attn_scores_mma,
                         cudaFuncAttributeMaxDynamicSharedMemorySize, ATTN_SMEM);
    cudaFuncSetAttribute(attn_o_mma,
                         cudaFuncAttributeMaxDynamicSharedMemorySize, ATTN_SMEM);

    float *x,*dx,*h,*dh,*q,*k,*v,*dq,*dk,*dv,*o,*dd,*u,*du,*sc,*dsc,*tt;
    cudaGetSymbolAddress((void**)&x,  g_x);
    cudaGetSymbolAddress((void**)&dx, g_dx);
    cudaGetSymbolAddress((void**)&h,  g_h);
    cudaGetSymbolAddress((void**)&dh, g_dh);
    cudaGetSymbolAddress((void**)&q,  g_q);
    cudaGetSymbolAddress((void**)&k,  g_k);
    cudaGetSymbolAddress((void**)&v,  g_v);
    cudaGetSymbolAddress((void**)&dq, g_dq);
    cudaGetSymbolAddress((void**)&dk, g_dk);
    cudaGetSymbolAddress((void**)&dv, g_dv);
    cudaGetSymbolAddress((void**)&o,  g_o);
    cudaGetSymbolAddress((void**)&dd, g_do);
    cudaGetSymbolAddress((void**)&u,  g_u);
    cudaGetSymbolAddress((void**)&du, g_du);
    cudaGetSymbolAddress((void**)&sc, g_sc);
    cudaGetSymbolAddress((void**)&dsc,g_dsc);
    cudaGetSymbolAddress((void**)&tt, g_t);

    unsigned *a1H,*a1L,*a2H,*a2L,*wH,*wL;
    cudaGetSymbolAddress((void**)&a1H, g_a1H);
    cudaGetSymbolAddress((void**)&a1L, g_a1L);
    cudaGetSymbolAddress((void**)&a2H, g_a2H);
    cudaGetSymbolAddress((void**)&a2L, g_a2L);
    cudaGetSymbolAddress((void**)&wH,  g_wH);
    cudaGetSymbolAddress((void**)&wL,  g_wL);

    // weight splits
    for (int l = 0; l < kL; l++) {
        size_t b0 = (size_t)l * WLAYER2;
        splitB(Wq + (size_t)l*kD*kD,  wH + b0,            wL + b0,            kD, kD);
        splitB(Wk + (size_t)l*kD*kD,  wH + b0 + DD2,      wL + b0 + DD2,      kD, kD);
        splitB(Wv + (size_t)l*kD*kD,  wH + b0 + 2*DD2,    wL + b0 + 2*DD2,    kD, kD);
        splitB(Wo + (size_t)l*kD*kD,  wH + b0 + 3*DD2,    wL + b0 + 3*DD2,    kD, kD);
        splitB(W1 + (size_t)l*kD*kFF, wH + b0 + 4*DD2,    wL + b0 + 4*DD2,    kD, kFF);
        splitB(W2 + (size_t)l*kFF*kD, wH + b0 + 4*DD2+DF2, wL + b0 + 4*DD2+DF2, kFF, kD);
    }
    size_t lmOff = (size_t)kL * WLAYER2;
    splitB(lmh, wH + lmOff, wL + lmOff, kD, kV);

    embed_kernel<<<dim3(kD/256, kM), 256>>>(ids, emb, x, dx);
    zero_kernel<<<(kM*kD/4 + 255)/256, 256>>>(dk, kM*kD/4);   // layer-0 dk = 0

    for (int l = 0; l < kL; l++) {
        size_t b0 = (size_t)l * WLAYER2;
        const unsigned *wqH = wH + b0,            *wqL = wL + b0;
        const unsigned *wkH = wH + b0 + DD2,      *wkL = wL + b0 + DD2;
        const unsigned *wvH = wH + b0 + 2*DD2,    *wvL = wL + b0 + 2*DD2;
        const unsigned *woH = wH + b0 + 3*DD2,    *woL = wL + b0 + 3*DD2;
        const unsigned *w1H = wH + b0 + 4*DD2,    *w1L = wL + b0 + 4*DD2;
        const unsigned *w2H = wH + b0 + 4*DD2+DF2,*w2L = wL + b0 + 4*DD2+DF2;

        rms_jvp_kernel<<<kM, 256>>>(x, dx, ln1 + (size_t)l*kD, h, dh, 0);
        splitA(h, a1H, a1L, kM, kD);

        hgemm(a1H, a1L, wqH, wqL, q,  kM, kD, kD, 0);
        hgemm(a1H, a1L, wkH, wkL, k,  kM, kD, kD, 0);
        hgemm(a1H, a1L, wvH, wvL, v,  kM, kD, kD, 0);
        if (l > 0) {
            // layer 0: dh == 0 exactly (dx == 0), so dq/dk/dv from GEMMs vanish
            splitA(dh, a2H, a2L, kM, kD);
            hgemm(a2H, a2L, wqH, wqL, dq, kM, kD, kD, 0);
            hgemm(a2H, a2L, wkH, wkL, dk, kM, kD, kD, 0);
            hgemm(a2H, a2L, wvH, wvL, dv, kM, kD, kD, 0);
        }

        int wr = (l == 0) ? 1 : 0;
        lora_t_kernel<<<dim3(kM, kR), 128>>>(h, Aq0 + (size_t)l*kR*kD, tt);
        lora_add_kernel<<<dim3(kD/256, kM), 256>>>(tt, Bq + (size_t)l*kD*kR, dq, wr);
        lora_t_kernel<<<dim3(kM, kR), 128>>>(h, Av0 + (size_t)l*kR*kD, tt);
        lora_add_kernel<<<dim3(kD/256, kM), 256>>>(tt, Bv + (size_t)l*kD*kR, dv, wr);

        attn_scores_mma<<<dim3(kS/64, kS/64, kBH), 256, ATTN_SMEM>>>(q, k, dq, dk, sc, dsc);
        softmax_jvp_kernel<<<dim3(kS, kBH), 256>>>(sc, dsc);
        attn_o_mma<<<dim3(kS/64, kBH), 256, ATTN_SMEM>>>(sc, dsc, v, dv, o, dd);

        splitA(o,  a1H, a1L, kM, kD);
        splitA(dd, a2H, a2L, kM, kD);
        hgemm(a1H, a1L, woH, woL, x,  kM, kD, kD, 1);
        hgemm(a2H, a2L, woH, woL, dx, kM, kD, kD, 1);

        rms_jvp_kernel<<<kM, 256>>>(x, dx, ln2 + (size_t)l*kD, h, dh, 0);
        splitA(h,  a1H, a1L, kM, kD);
        splitA(dh, a2H, a2L, kM, kD);
        hgemm(a1H, a1L, w1H, w1L, u,  kM, kFF, kD, 0);
        hgemm(a2H, a2L, w1H, w1L, du, kM, kFF, kD, 0);
        gelu_split_kernel<<<dim3(kFF/64, kM/128), 256>>>(u, du, a1H, a1L, a2H, a2L, kM, kFF);
        hgemm(a1H, a1L, w2H, w2L, x,  kM, kD, kFF, 1);
        hgemm(a2H, a2L, w2H, w2L, dx, kM, kD, kFF, 1);
    }

    rms_jvp_kernel<<<kM, 256>>>(x, dx, lnf, h, h, 1);
    splitA(h, a1H, a1L, kM, kD);
    hgemm(a1H, a1L, wH + lmOff, wL + lmOff, out, kM, kV, kD, 0);
}